// round 7
// baseline (speedup 1.0000x reference)
#include <cuda_runtime.h>
#include <cuda_bf16.h>
#include <cstdint>

#define T_LEN 8192
#define BATCH 2
#define CDIM 1024
#define NHEAD 16
#define HDIM 64
#define WINSZ 256
#define NWIN_TOT 64
#define NTOK (BATCH * T_LEN)     // 16384

// ---------------- scratch ----------------------------------------------------
__device__ float g_Q[(size_t)NTOK * CDIM];
__device__ float g_K[(size_t)NTOK * CDIM];
__device__ float g_V[(size_t)NTOK * CDIM];
__device__ float g_AO[(size_t)NTOK * CDIM];       // attn out, tf32-rounded, k-permuted
__device__ float g_XT[(size_t)NTOK * CDIM];       // x, tf32-rounded, k-permuted
__device__ float g_WT[4][(size_t)CDIM * CDIM];    // weights, tf32-rounded, k-permuted
__device__ __nv_bfloat16 g_QHL[(size_t)NTOK * NHEAD * 128];
__device__ __nv_bfloat16 g_KHL[(size_t)NTOK * NHEAD * 128];
__device__ __nv_bfloat16 g_VHL[(size_t)NTOK * NHEAD * 128];
__device__ unsigned char g_attend[NWIN_TOT * 512];
__device__ int g_maskmode;

// ---------------- helpers ------------------------------------------------------
__device__ __forceinline__ uint32_t smem_u32(const void* p) {
    uint32_t a;
    asm("{ .reg .u64 t; cvta.to.shared.u64 t, %1; cvt.u32.u64 %0, t; }" : "=r"(a) : "l"(p));
    return a;
}
__device__ __forceinline__ void cp16(uint32_t dst, const void* src) {
    asm volatile("cp.async.cg.shared.global [%0], [%1], 16;" :: "r"(dst), "l"(src));
}
__device__ __forceinline__ void cp16z(uint32_t dst, const void* src, uint32_t sz) {
    asm volatile("cp.async.cg.shared.global [%0], [%1], 16, %2;" :: "r"(dst), "l"(src), "r"(sz));
}
__device__ __forceinline__ void cp_commit() { asm volatile("cp.async.commit_group;"); }
template <int N> __device__ __forceinline__ void cp_wait() {
    asm volatile("cp.async.wait_group %0;" :: "n"(N));
}
__device__ __forceinline__ void ldsm4(uint32_t (&r)[4], uint32_t addr) {
    asm volatile("ldmatrix.sync.aligned.m8n8.x4.shared.b16 {%0,%1,%2,%3}, [%4];"
                 : "=r"(r[0]), "=r"(r[1]), "=r"(r[2]), "=r"(r[3]) : "r"(addr));
}
__device__ __forceinline__ void ldsm4t(uint32_t (&r)[4], uint32_t addr) {
    asm volatile("ldmatrix.sync.aligned.m8n8.x4.trans.shared.b16 {%0,%1,%2,%3}, [%4];"
                 : "=r"(r[0]), "=r"(r[1]), "=r"(r[2]), "=r"(r[3]) : "r"(addr));
}
__device__ __forceinline__ void mma16816(float (&c)[4], const uint32_t (&a)[4],
                                         uint32_t b0, uint32_t b1) {
    asm volatile(
        "mma.sync.aligned.m16n8k16.row.col.f32.bf16.bf16.f32 "
        "{%0,%1,%2,%3}, {%4,%5,%6,%7}, {%8,%9}, {%0,%1,%2,%3};"
        : "+f"(c[0]), "+f"(c[1]), "+f"(c[2]), "+f"(c[3])
        : "r"(a[0]), "r"(a[1]), "r"(a[2]), "r"(a[3]), "r"(b0), "r"(b1));
}
__device__ __forceinline__ void mma_tf32(float (&c)[4], const uint32_t (&a)[4],
                                         uint32_t b0, uint32_t b1) {
    asm volatile(
        "mma.sync.aligned.m16n8k8.row.col.f32.tf32.tf32.f32 "
        "{%0,%1,%2,%3}, {%4,%5,%6,%7}, {%8,%9}, {%0,%1,%2,%3};"
        : "+f"(c[0]), "+f"(c[1]), "+f"(c[2]), "+f"(c[3])
        : "r"(a[0]), "r"(a[1]), "r"(a[2]), "r"(a[3]), "r"(b0), "r"(b1));
}
__device__ __forceinline__ uint32_t pack_bf16(float lo, float hi) {
    uint32_t r;
    asm("cvt.rn.bf16x2.f32 %0, %1, %2;" : "=r"(r) : "f"(hi), "f"(lo));
    return r;
}
__device__ __forceinline__ float bf_lo(uint32_t u) { return __uint_as_float(u << 16); }
__device__ __forceinline__ float bf_hi(uint32_t u) { return __uint_as_float(u & 0xffff0000u); }
__device__ __forceinline__ float rna_tf32(float f) {
    uint32_t r;
    asm("cvt.rna.tf32.f32 %0, %1;" : "=r"(r) : "f"(f));
    return __uint_as_float(r);
}

// ---------------- tf32 round + k-block permute pass ---------------------------
// Within each 32-col block: k' = (k&3)*8 + (k>>2). Scatter from contiguous reads.
__global__ void round_perm(const float* __restrict__ in, float* __restrict__ out) {
    int i = blockIdx.x * blockDim.x + threadIdx.x;   // one float4
    int row = i >> 8;
    int q = i & 255;
    float4 v = ((const float4*)in)[i];
    float vals[4] = {rna_tf32(v.x), rna_tf32(v.y), rna_tf32(v.z), rna_tf32(v.w)};
    int blk = q >> 3;
    int sub = q & 7;            // kb = sub*4 + j  ->  k' = j*8 + sub
    float* o = out + (size_t)row * CDIM + blk * 32 + sub;
#pragma unroll
    for (int j = 0; j < 4; j++) o[j * 8] = vals[j];
}

// ---------------- TF32 GEMM (k-permuted operands) ------------------------------
// C[M,1024] = A[M,1024p] @ W[1024,1024p]^T + bias. CTA 128x128, BK=32.
// Inner loop: 24 LDS.128 + 64 MMA per warp-chunk; single __syncthreads per chunk.
#define GK 1024
#define GCH 32
#define GSTG 36864
#define GB_OFF 18432
#define SMEM_GEMM (3 * GSTG)

__device__ __forceinline__ void g_load_chunk(uint32_t stage, const float* Arow,
                                             const float* Brow, int kbase, int tid) {
#pragma unroll
    for (int i = 0; i < 4; i++) {
        int f = tid + i * 256;
        int rr = f >> 3, seg = f & 7;
        uint32_t dst = stage + (uint32_t)rr * 144 + (uint32_t)seg * 16;
        cp16(dst, Arow + (size_t)rr * GK + kbase + seg * 4);
        cp16(dst + GB_OFF, Brow + (size_t)rr * GK + kbase + seg * 4);
    }
}

__global__ void __launch_bounds__(256) gemm_tf32(const float* __restrict__ A,
        const float* __restrict__ W, const float* __restrict__ bias,
        float* __restrict__ C) {
    extern __shared__ char dsm[];
    int tid = threadIdx.x;
    int wid = tid >> 5, lane = tid & 31;
    int row0 = blockIdx.y * 128;
    int col0 = blockIdx.x * 128;
    int m0 = (wid & 3) * 32;
    int n0 = (wid >> 2) * 64;
    int gp = lane >> 2;
    int ci = lane & 3;

    const float* Arow = A + (size_t)row0 * GK;
    const float* Brow = W + (size_t)col0 * GK;

    // fragment base offsets in a stage (permuted k: thread's data contiguous)
    uint32_t aBase[2], bBase[8];
#pragma unroll
    for (int mi = 0; mi < 2; mi++)
        aBase[mi] = (uint32_t)(m0 + mi * 16 + gp) * 144 + (uint32_t)ci * 32;
#pragma unroll
    for (int nt = 0; nt < 8; nt++)
        bBase[nt] = (uint32_t)GB_OFF + (uint32_t)(n0 + nt * 8 + gp) * 144 + (uint32_t)ci * 32;

    float acc[2][8][4];
#pragma unroll
    for (int mi = 0; mi < 2; mi++)
#pragma unroll
        for (int nt = 0; nt < 8; nt++)
#pragma unroll
            for (int j = 0; j < 4; j++) acc[mi][nt][j] = 0.0f;

    uint32_t sb = smem_u32(dsm);
    g_load_chunk(sb, Arow, Brow, 0, tid);
    cp_commit();
    g_load_chunk(sb + GSTG, Arow, Brow, 32, tid);
    cp_commit();

    for (int c = 0; c < GCH; c++) {
        cp_wait<1>();
        __syncthreads();
        if (c + 2 < GCH)
            g_load_chunk(sb + (uint32_t)((c + 2) % 3) * GSTG, Arow, Brow, (c + 2) * 32, tid);
        cp_commit();          // always commit -> uniform wait depth

        const char* stg = dsm + (size_t)(c % 3) * GSTG;
#pragma unroll
        for (int pp = 0; pp < 2; pp++) {              // two k8-pairs per chunk
            float4 Bv[8];
#pragma unroll
            for (int nt = 0; nt < 8; nt++)
                Bv[nt] = *(const float4*)(stg + bBase[nt] + pp * 16);
            float4 A0[2], A1[2];
#pragma unroll
            for (int mi = 0; mi < 2; mi++) {
                A0[mi] = *(const float4*)(stg + aBase[mi] + pp * 16);
                A1[mi] = *(const float4*)(stg + aBase[mi] + 1152 + pp * 16);
            }
#pragma unroll
            for (int ksl = 0; ksl < 2; ksl++) {
#pragma unroll
                for (int mi = 0; mi < 2; mi++) {
                    const float* a0 = (const float*)&A0[mi];
                    const float* a1 = (const float*)&A1[mi];
                    uint32_t a[4];
                    a[0] = __float_as_uint(a0[ksl * 2]);
                    a[1] = __float_as_uint(a1[ksl * 2]);
                    a[2] = __float_as_uint(a0[ksl * 2 + 1]);
                    a[3] = __float_as_uint(a1[ksl * 2 + 1]);
#pragma unroll
                    for (int nt = 0; nt < 8; nt++) {
                        const float* bv = (const float*)&Bv[nt];
                        mma_tf32(acc[mi][nt], a,
                                 __float_as_uint(bv[ksl * 2]),
                                 __float_as_uint(bv[ksl * 2 + 1]));
                    }
                }
            }
        }
    }

    int cl = ci * 2;
#pragma unroll
    for (int mi = 0; mi < 2; mi++) {
#pragma unroll
        for (int nt = 0; nt < 8; nt++) {
            int gcol = col0 + n0 + nt * 8 + cl;
            float b0 = bias[gcol], b1 = bias[gcol + 1];
            int r0 = row0 + m0 + mi * 16 + gp;
            float2 v0 = make_float2(acc[mi][nt][0] + b0, acc[mi][nt][1] + b1);
            float2 v1 = make_float2(acc[mi][nt][2] + b0, acc[mi][nt][3] + b1);
            *(float2*)(C + (size_t)r0 * CDIM + gcol) = v0;
            *(float2*)(C + (size_t)(r0 + 8) * CDIM + gcol) = v1;
        }
    }
}

// ---------------- mask dtype detection + attend mask -------------------------
__global__ void detect_mask(const unsigned int* __restrict__ m) {
    __shared__ int okf, oki;
    if (threadIdx.x == 0) { okf = 1; oki = 1; }
    __syncthreads();
    for (int i = threadIdx.x; i < 4096; i += blockDim.x) {
        unsigned int w = m[i];
        if (w != 0u && w != 0x3f800000u) okf = 0;
        if (w > 1u) oki = 0;
    }
    __syncthreads();
    if (threadIdx.x == 0) g_maskmode = okf ? 2 : (oki ? 1 : 0);
}

__global__ void build_attend(const void* __restrict__ pm) {
    int w = blockIdx.x;
    int b = w >> 5;
    int wi = w & 31;
    int j = threadIdx.x;
    int p = wi * WINSZ - 128 + j;
    int attend = 1;
    if ((unsigned)p < (unsigned)T_LEN) {
        int mm = g_maskmode;
        size_t im = (size_t)b * T_LEN + p;
        int v;
        if (mm == 0)      v = ((const unsigned char*)pm)[im] != 0;
        else if (mm == 1) v = ((const int*)pm)[im] != 0;
        else              v = ((const float*)pm)[im] != 0.0f;
        attend = !v;
    }
    __shared__ int allb;
    if (j == 0) allb = 1;
    __syncthreads();
    if (!attend) allb = 0;
    __syncthreads();
    if (j == 0 && allb) attend = 0;
    g_attend[w * 512 + j] = (unsigned char)attend;
}

// ---------------- fused rope + split (Q,K) / split (V) ------------------------
__global__ void rope_split(const float* __restrict__ Q, const float* __restrict__ K,
                           const float* __restrict__ V,
                           const float* __restrict__ cosT, const float* __restrict__ sinT,
                           __nv_bfloat16* __restrict__ QHL, __nv_bfloat16* __restrict__ KHL,
                           __nv_bfloat16* __restrict__ VHL) {
    int idx = blockIdx.x * blockDim.x + threadIdx.x;
    int z = blockIdx.y;
    const float* src = (z == 0) ? Q : ((z == 1) ? K : V);
    __nv_bfloat16* dst = (z == 0) ? QHL : ((z == 1) ? KHL : VHL);
    int token = idx >> 9;
    int r = idx & 511;
    int hh = r >> 5;
    int d = r & 31;
    int pos = token & (T_LEN - 1);
    size_t base = (size_t)token * CDIM + hh * HDIM;
    float a = src[base + d];
    float bv = src[base + d + 32];
    float o1, o2;
    if (z < 2) {
        float c1 = cosT[pos * HDIM + d], s1 = sinT[pos * HDIM + d];
        float c2 = cosT[pos * HDIM + d + 32], s2 = sinT[pos * HDIM + d + 32];
        o1 = a * c1 - bv * s1;
        o2 = bv * c2 + a * s2;
    } else { o1 = a; o2 = bv; }
    size_t ob = ((size_t)token * NHEAD + hh) * 128;
    __nv_bfloat16 h1 = __float2bfloat16_rn(o1);
    __nv_bfloat16 h2 = __float2bfloat16_rn(o2);
    dst[ob + d] = h1;
    dst[ob + d + 32] = h2;
    dst[ob + 64 + d] = __float2bfloat16_rn(o1 - __bfloat162float(h1));
    dst[ob + 96 + d] = __float2bfloat16_rn(o2 - __bfloat162float(h2));
}

// ---------------- tensor-core windowed attention ------------------------------
#define ATT_Q_LO 32768
#define ATT_STG 65536
#define ATT_BIAS 131072
#define SMEM_ATTN (1024 + 131072 + 256)

__device__ __forceinline__ void load_kv_chunk(uint32_t stg, const __nv_bfloat16* KHL,
        const __nv_bfloat16* VHL, int b, int h, int p0, int tid) {
#pragma unroll
    for (int i = 0; i < 2; i++) {
        int f = tid + i * 256;
        int r = f >> 3, seg = f & 7;
        int p = p0 + r;
        uint32_t ok = ((unsigned)p < (unsigned)T_LEN) ? 16u : 0u;
        int pc = (p < 0) ? 0 : ((p >= T_LEN) ? (T_LEN - 1) : p);
        const __nv_bfloat16* kk = KHL + (((size_t)(b * T_LEN + pc) * NHEAD + h) << 7) + seg * 8;
        const __nv_bfloat16* vv = VHL + (((size_t)(b * T_LEN + pc) * NHEAD + h) << 7) + seg * 8;
        uint32_t sw = (uint32_t)r * 128 + (uint32_t)(((seg ^ (r & 7)) << 4));
        cp16z(stg + sw, kk, ok);
        cp16z(stg + 8192 + sw, kk + 64, ok);
        cp16z(stg + 16384 + sw, vv, ok);
        cp16z(stg + 24576 + sw, vv + 64, ok);
    }
}

__global__ void __launch_bounds__(256) attn_mma(
        const __nv_bfloat16* __restrict__ QHL, const __nv_bfloat16* __restrict__ KHL,
        const __nv_bfloat16* __restrict__ VHL, float* __restrict__ AO) {
    extern __shared__ char sm[];
    char* smA = (char*)(((uintptr_t)sm + 1023) & ~(uintptr_t)1023);
    uint32_t sb = smem_u32(smA);
    float* biasP = (float*)(smA + ATT_BIAS);

    int h = blockIdx.x, w = blockIdx.y;
    int b = w >> 5, wi = w & 31;
    int tid = threadIdx.x, wid = tid >> 5, lane = tid & 31;
    int w0 = wid * 32;

    int rA = (lane & 7) + ((lane >> 3) & 1) * 8;
    int ksegA = lane >> 4;
    int rB = (lane & 7) + ((lane >> 4) << 3);
    int ksegB = (lane >> 3) & 1;
    int krV = (lane & 7) + ((lane >> 4) << 3);
    int nsegV = (lane >> 3) & 1;

#pragma unroll
    for (int i = 0; i < 8; i++) {
        int f = tid + i * 256;
        int r = f >> 3, seg = f & 7;
        const __nv_bfloat16* q = QHL + (((size_t)(b * T_LEN + wi * 256 + r) * NHEAD + h) << 7)
                                 + seg * 8;
        uint32_t sw = (uint32_t)r * 128 + (uint32_t)(((seg ^ (r & 7)) << 4));
        cp16(sb + sw, q);
        cp16(sb + ATT_Q_LO + sw, q + 64);
    }
    load_kv_chunk(sb + ATT_STG, KHL, VHL, b, h, wi * 256 - 128, tid);
    cp_commit();
    load_kv_chunk(sb + ATT_STG + 32768, KHL, VHL, b, h, wi * 256 - 64, tid);
    cp_commit();

    float O[2][8][4];
#pragma unroll
    for (int mi = 0; mi < 2; mi++)
#pragma unroll
        for (int nt = 0; nt < 8; nt++)
#pragma unroll
            for (int j = 0; j < 4; j++) O[mi][nt][j] = 0.0f;
    float mrow[4] = {-3e38f, -3e38f, -3e38f, -3e38f};
    float lrow[4] = {0.f, 0.f, 0.f, 0.f};

    for (int c = 0; c < 8; c++) {
        if (c < 6) { cp_wait<1>(); } else { cp_wait<0>(); }
        if (tid < 64)
            biasP[tid] = g_attend[w * 512 + c * 64 + tid] ? 0.0f : -1e30f;
        __syncthreads();

        uint32_t stg = sb + ATT_STG + (uint32_t)(c & 1) * 32768u;

        float S[2][8][4];
#pragma unroll
        for (int mi = 0; mi < 2; mi++)
#pragma unroll
            for (int nt = 0; nt < 8; nt++)
#pragma unroll
                for (int j = 0; j < 4; j++) S[mi][nt][j] = 0.0f;

#pragma unroll
        for (int pass = 0; pass < 3; pass++) {
            uint32_t qoff = (pass == 2) ? (uint32_t)ATT_Q_LO : 0u;
            uint32_t koff = (pass == 1) ? 8192u : 0u;
#pragma unroll
            for (int step = 0; step < 4; step++) {
                uint32_t kb[4][4];
#pragma unroll
                for (int g = 0; g < 4; g++) {
                    int row = g * 16 + rB;
                    ldsm4(kb[g], stg + koff + (uint32_t)row * 128
                          + (uint32_t)(((step * 2 + ksegB) ^ (row & 7)) << 4));
                }
#pragma unroll
                for (int mi = 0; mi < 2; mi++) {
                    int rowQ = w0 + mi * 16 + rA;
                    uint32_t qf[4];
                    ldsm4(qf, sb + qoff + (uint32_t)rowQ * 128
                          + (uint32_t)(((step * 2 + ksegA) ^ (rowQ & 7)) << 4));
#pragma unroll
                    for (int nt = 0; nt < 8; nt++)
                        mma16816(S[mi][nt], qf, kb[nt >> 1][(nt & 1) * 2],
                                 kb[nt >> 1][(nt & 1) * 2 + 1]);
                }
            }
        }

        float2 bias[8];
#pragma unroll
        for (int nt = 0; nt < 8; nt++)
            bias[nt] = *(float2*)&biasP[nt * 8 + 2 * (lane & 3)];
#pragma unroll
        for (int mi = 0; mi < 2; mi++)
#pragma unroll
            for (int nt = 0; nt < 8; nt++) {
                S[mi][nt][0] = fmaf(S[mi][nt][0], 0.125f, bias[nt].x);
                S[mi][nt][1] = fmaf(S[mi][nt][1], 0.125f, bias[nt].y);
                S[mi][nt][2] = fmaf(S[mi][nt][2], 0.125f, bias[nt].x);
                S[mi][nt][3] = fmaf(S[mi][nt][3], 0.125f, bias[nt].y);
            }
#pragma unroll
        for (int mi = 0; mi < 2; mi++)
#pragma unroll
            for (int hh = 0; hh < 2; hh++) {
                int s = mi * 2 + hh;
                float rm = -3e38f;
#pragma unroll
                for (int nt = 0; nt < 8; nt++)
                    rm = fmaxf(rm, fmaxf(S[mi][nt][hh * 2], S[mi][nt][hh * 2 + 1]));
                rm = fmaxf(rm, __shfl_xor_sync(0xffffffffu, rm, 1));
                rm = fmaxf(rm, __shfl_xor_sync(0xffffffffu, rm, 2));
                float mn = fmaxf(mrow[s], rm);
                float sc = __expf(mrow[s] - mn);
                mrow[s] = mn;
                float ls = 0.0f;
#pragma unroll
                for (int nt = 0; nt < 8; nt++) {
                    float p0 = __expf(S[mi][nt][hh * 2] - mn);
                    float p1 = __expf(S[mi][nt][hh * 2 + 1] - mn);
                    S[mi][nt][hh * 2] = p0;
                    S[mi][nt][hh * 2 + 1] = p1;
                    ls += p0 + p1;
                    O[mi][nt][hh * 2] *= sc;
                    O[mi][nt][hh * 2 + 1] *= sc;
                }
                lrow[s] = lrow[s] * sc + ls;
            }

#pragma unroll
        for (int step = 0; step < 4; step++) {
            uint32_t ah[2][4], al[2][4];
#pragma unroll
            for (int mi = 0; mi < 2; mi++)
#pragma unroll
                for (int t2 = 0; t2 < 2; t2++) {
                    float p0 = S[mi][2 * step + t2][0], p1 = S[mi][2 * step + t2][1];
                    float p2 = S[mi][2 * step + t2][2], p3 = S[mi][2 * step + t2][3];
                    uint32_t hA = pack_bf16(p0, p1);
                    uint32_t hB = pack_bf16(p2, p3);
                    ah[mi][t2 * 2] = hA;
                    ah[mi][t2 * 2 + 1] = hB;
                    al[mi][t2 * 2] = pack_bf16(p0 - bf_lo(hA), p1 - bf_hi(hA));
                    al[mi][t2 * 2 + 1] = pack_bf16(p2 - bf_lo(hB), p3 - bf_hi(hB));
                }
            uint32_t vb[4][4];
#pragma unroll
            for (int g = 0; g < 4; g++) {
                int vrow = step * 16 + krV;
                int seg = g * 2 + nsegV;
                ldsm4t(vb[g], stg + 16384u + (uint32_t)vrow * 128
                       + (uint32_t)(((seg ^ (vrow & 7)) << 4)));
            }
#pragma unroll
            for (int mi = 0; mi < 2; mi++)
#pragma unroll
                for (int nt = 0; nt < 8; nt++) {
                    uint32_t b0 = vb[nt >> 1][nt & 1], b1 = vb[nt >> 1][(nt & 1) + 2];
                    mma16816(O[mi][nt], ah[mi], b0, b1);
                    mma16816(O[mi][nt], al[mi], b0, b1);
                }
#pragma unroll
            for (int g = 0; g < 4; g++) {
                int vrow = step * 16 + krV;
                int seg = g * 2 + nsegV;
                ldsm4t(vb[g], stg + 24576u + (uint32_t)vrow * 128
                       + (uint32_t)(((seg ^ (vrow & 7)) << 4)));
            }
#pragma unroll
            for (int mi = 0; mi < 2; mi++)
#pragma unroll
                for (int nt = 0; nt < 8; nt++)
                    mma16816(O[mi][nt], ah[mi], vb[nt >> 1][nt & 1],
                             vb[nt >> 1][(nt & 1) + 2]);
        }

        __syncthreads();
        if (c + 2 < 8) {
            load_kv_chunk(sb + ATT_STG + (uint32_t)(c & 1) * 32768u, KHL, VHL, b, h,
                          wi * 256 - 128 + (c + 2) * 64, tid);
            cp_commit();
        }
    }

#pragma unroll
    for (int s = 0; s < 4; s++) {
        lrow[s] += __shfl_xor_sync(0xffffffffu, lrow[s], 1);
        lrow[s] += __shfl_xor_sync(0xffffffffu, lrow[s], 2);
        lrow[s] = 1.0f / lrow[s];
    }
    int rr = lane >> 2, cc = 2 * (lane & 3);
#pragma unroll
    for (int mi = 0; mi < 2; mi++)
#pragma unroll
        for (int nt = 0; nt < 8; nt++) {
            int tok0 = b * T_LEN + wi * 256 + w0 + mi * 16 + rr;
            int col = h * 64 + nt * 8 + cc;
            // permuted k-layout store: colp for cc, colp+8 for cc+1
            int blk = col >> 5, kb = col & 31;
            int colp = (blk << 5) + (kb & 3) * 8 + (kb >> 2);
            float i0 = lrow[mi * 2], i1 = lrow[mi * 2 + 1];
            float* a0 = AO + (size_t)tok0 * CDIM;
            float* a1 = AO + (size_t)(tok0 + 8) * CDIM;
            a0[colp]     = rna_tf32(O[mi][nt][0] * i0);
            a0[colp + 8] = rna_tf32(O[mi][nt][1] * i0);
            a1[colp]     = rna_tf32(O[mi][nt][2] * i1);
            a1[colp + 8] = rna_tf32(O[mi][nt][3] * i1);
        }
}

// ---------------- launch --------------------------------------------------------
extern "C" void kernel_launch(void* const* d_in, const int* in_sizes, int n_in,
                              void* d_out, int out_size) {
    const float* x    = (const float*)d_in[0];
    const void*  pm   = d_in[1];
    const float* cosT = (const float*)d_in[2];
    const float* sinT = (const float*)d_in[3];
    const float* Wq   = (const float*)d_in[4];
    const float* bq   = (const float*)d_in[5];
    const float* Wk   = (const float*)d_in[6];
    const float* bk   = (const float*)d_in[7];
    const float* Wv   = (const float*)d_in[8];
    const float* bv   = (const float*)d_in[9];
    const float* Wo   = (const float*)d_in[10];
    const float* bo   = (const float*)d_in[11];
    float* out = (float*)d_out;

    float *Qp, *Kp, *Vp, *AOp, *XT, *WT;
    __nv_bfloat16 *QHL, *KHL, *VHL;
    cudaGetSymbolAddress((void**)&Qp, g_Q);
    cudaGetSymbolAddress((void**)&Kp, g_K);
    cudaGetSymbolAddress((void**)&Vp, g_V);
    cudaGetSymbolAddress((void**)&AOp, g_AO);
    cudaGetSymbolAddress((void**)&XT, g_XT);
    cudaGetSymbolAddress((void**)&WT, g_WT);
    cudaGetSymbolAddress((void**)&QHL, g_QHL);
    cudaGetSymbolAddress((void**)&KHL, g_KHL);
    cudaGetSymbolAddress((void**)&VHL, g_VHL);

    cudaFuncSetAttribute(gemm_tf32, cudaFuncAttributeMaxDynamicSharedMemorySize, SMEM_GEMM);
    cudaFuncSetAttribute(attn_mma, cudaFuncAttributeMaxDynamicSharedMemorySize, SMEM_ATTN);

    detect_mask<<<1, 256>>>((const unsigned int*)pm);
    build_attend<<<NWIN_TOT, 512>>>(pm);

    // pre-round to tf32 + k-block permute
    round_perm<<<NTOK * CDIM / 1024, 256>>>(x, XT);
    round_perm<<<CDIM * CDIM / 1024, 256>>>(Wq, WT + 0 * (size_t)CDIM * CDIM);
    round_perm<<<CDIM * CDIM / 1024, 256>>>(Wk, WT + 1 * (size_t)CDIM * CDIM);
    round_perm<<<CDIM * CDIM / 1024, 256>>>(Wv, WT + 2 * (size_t)CDIM * CDIM);
    round_perm<<<CDIM * CDIM / 1024, 256>>>(Wo, WT + 3 * (size_t)CDIM * CDIM);

    dim3 gg(CDIM / 128, NTOK / 128);
    gemm_tf32<<<gg, 256, SMEM_GEMM>>>(XT, WT + 0 * (size_t)CDIM * CDIM, bq, Qp);
    gemm_tf32<<<gg, 256, SMEM_GEMM>>>(XT, WT + 1 * (size_t)CDIM * CDIM, bk, Kp);
    gemm_tf32<<<gg, 256, SMEM_GEMM>>>(XT, WT + 2 * (size_t)CDIM * CDIM, bv, Vp);

    dim3 rg((NTOK * 512) / 256, 3);
    rope_split<<<rg, 256>>>(Qp, Kp, Vp, cosT, sinT, QHL, KHL, VHL);

    attn_mma<<<dim3(NHEAD, NWIN_TOT), 256, SMEM_ATTN>>>(QHL, KHL, VHL, AOp);

    gemm_tf32<<<gg, 256, SMEM_GEMM>>>(AOp, WT + 3 * (size_t)CDIM * CDIM, bo, out);
}

// round 8
// speedup vs baseline: 1.6254x; 1.6254x over previous
#include <cuda_runtime.h>
#include <cuda_bf16.h>
#include <cuda_fp16.h>
#include <cstdint>

#define T_LEN 8192
#define BATCH 2
#define CDIM 1024
#define NHEAD 16
#define HDIM 64
#define WINSZ 256
#define NWIN_TOT 64
#define NTOK (BATCH * T_LEN)     // 16384

// ---------------- scratch ----------------------------------------------------
__device__ float g_Q[(size_t)NTOK * CDIM];
__device__ float g_K[(size_t)NTOK * CDIM];
__device__ float g_V[(size_t)NTOK * CDIM];
__device__ __half g_XH[(size_t)NTOK * CDIM];        // x, fp16
__device__ __half g_AOH[(size_t)NTOK * CDIM];       // attn out, fp16
__device__ __half g_WH[4][(size_t)CDIM * CDIM];     // weights, fp16
__device__ __nv_bfloat16 g_QHL[(size_t)NTOK * NHEAD * 128];
__device__ __nv_bfloat16 g_KHL[(size_t)NTOK * NHEAD * 128];
__device__ __nv_bfloat16 g_VHL[(size_t)NTOK * NHEAD * 128];
__device__ unsigned char g_attend[NWIN_TOT * 512];
__device__ int g_maskmode;

// ---------------- helpers ------------------------------------------------------
__device__ __forceinline__ uint32_t smem_u32(const void* p) {
    uint32_t a;
    asm("{ .reg .u64 t; cvta.to.shared.u64 t, %1; cvt.u32.u64 %0, t; }" : "=r"(a) : "l"(p));
    return a;
}
__device__ __forceinline__ void cp16(uint32_t dst, const void* src) {
    asm volatile("cp.async.cg.shared.global [%0], [%1], 16;" :: "r"(dst), "l"(src));
}
__device__ __forceinline__ void cp16z(uint32_t dst, const void* src, uint32_t sz) {
    asm volatile("cp.async.cg.shared.global [%0], [%1], 16, %2;" :: "r"(dst), "l"(src), "r"(sz));
}
__device__ __forceinline__ void cp_commit() { asm volatile("cp.async.commit_group;"); }
template <int N> __device__ __forceinline__ void cp_wait() {
    asm volatile("cp.async.wait_group %0;" :: "n"(N));
}
__device__ __forceinline__ void ldsm4(uint32_t (&r)[4], uint32_t addr) {
    asm volatile("ldmatrix.sync.aligned.m8n8.x4.shared.b16 {%0,%1,%2,%3}, [%4];"
                 : "=r"(r[0]), "=r"(r[1]), "=r"(r[2]), "=r"(r[3]) : "r"(addr));
}
__device__ __forceinline__ void ldsm4t(uint32_t (&r)[4], uint32_t addr) {
    asm volatile("ldmatrix.sync.aligned.m8n8.x4.trans.shared.b16 {%0,%1,%2,%3}, [%4];"
                 : "=r"(r[0]), "=r"(r[1]), "=r"(r[2]), "=r"(r[3]) : "r"(addr));
}
__device__ __forceinline__ void mma16816(float (&c)[4], const uint32_t (&a)[4],
                                         uint32_t b0, uint32_t b1) {
    asm volatile(
        "mma.sync.aligned.m16n8k16.row.col.f32.bf16.bf16.f32 "
        "{%0,%1,%2,%3}, {%4,%5,%6,%7}, {%8,%9}, {%0,%1,%2,%3};"
        : "+f"(c[0]), "+f"(c[1]), "+f"(c[2]), "+f"(c[3])
        : "r"(a[0]), "r"(a[1]), "r"(a[2]), "r"(a[3]), "r"(b0), "r"(b1));
}
__device__ __forceinline__ void mma16816h(float (&c)[4], const uint32_t (&a)[4],
                                          uint32_t b0, uint32_t b1) {
    asm volatile(
        "mma.sync.aligned.m16n8k16.row.col.f32.f16.f16.f32 "
        "{%0,%1,%2,%3}, {%4,%5,%6,%7}, {%8,%9}, {%0,%1,%2,%3};"
        : "+f"(c[0]), "+f"(c[1]), "+f"(c[2]), "+f"(c[3])
        : "r"(a[0]), "r"(a[1]), "r"(a[2]), "r"(a[3]), "r"(b0), "r"(b1));
}
__device__ __forceinline__ uint32_t pack_bf16(float lo, float hi) {
    uint32_t r;
    asm("cvt.rn.bf16x2.f32 %0, %1, %2;" : "=r"(r) : "f"(hi), "f"(lo));
    return r;
}
__device__ __forceinline__ float bf_lo(uint32_t u) { return __uint_as_float(u << 16); }
__device__ __forceinline__ float bf_hi(uint32_t u) { return __uint_as_float(u & 0xffff0000u); }

// ---------------- fp32 -> fp16 conversion pass ---------------------------------
__global__ void to_half(const float* __restrict__ in, __half* __restrict__ out) {
    int i = blockIdx.x * blockDim.x + threadIdx.x;   // one float4
    float4 v = ((const float4*)in)[i];
    __half2 h01 = __floats2half2_rn(v.x, v.y);
    __half2 h23 = __floats2half2_rn(v.z, v.w);
    ((__half2*)out)[2 * i] = h01;
    ((__half2*)out)[2 * i + 1] = h23;
}

// ---------------- fp16 GEMM: C[M,1024] = A[M,1024] @ W[1024,1024]^T + bias ----
// CTA tile 128x128, BK=64 halves (one SW128 atom row), 3-stage cp.async ring,
// 8 warps (4M x 2N), warp tile 32x64 via m16n8k16.  (R3-proven skeleton.)
#define GK 1024
#define CH 16                     // 1024 / 64
#define NST 3
#define STAGE_B 32768             // A 16KB + B 16KB
#define SMEM_GEMM (NST * STAGE_B)

__device__ __forceinline__ void load_chunk(uint32_t stage, const __half* Arow,
                                           const __half* Brow, int kbase, int tid) {
#pragma unroll
    for (int i = 0; i < 4; i++) {
        int f = tid + i * 256;            // 0..1023 = 128 rows x 8 segs
        int rr = f >> 3, seg = f & 7;
        uint32_t off = rr * 128 + seg * 16;
        uint32_t sw = off ^ ((off >> 3) & 0x70);
        cp16(stage + sw, Arow + (size_t)rr * GK + kbase + seg * 8);
        cp16(stage + 16384 + sw, Brow + (size_t)rr * GK + kbase + seg * 8);
    }
}

__global__ void __launch_bounds__(256) gemm_f16(const __half* __restrict__ A,
        const __half* __restrict__ Bw, const float* __restrict__ bias,
        float* __restrict__ C) {
    extern __shared__ char dsm[];
    uint32_t sbase = smem_u32(dsm);

    int tid = threadIdx.x;
    int wid = tid >> 5, lane = tid & 31;
    int row0 = blockIdx.y * 128;
    int col0 = blockIdx.x * 128;
    int m0 = (wid & 3) * 32;
    int n0 = (wid >> 2) * 64;

    const __half* Arow = A + (size_t)row0 * GK;
    const __half* Brow = Bw + (size_t)col0 * GK;

    int rA = m0 + (lane & 7) + ((lane >> 3) & 1) * 8;
    int ksegA = lane >> 4;
    int swA = rA & 7;
    int rB = n0 + (lane & 7) + ((lane >> 4) << 3);
    int ksegB = (lane >> 3) & 1;
    int swB = rB & 7;

    uint32_t aRowOff[2], bRowOff[4];
#pragma unroll
    for (int mi = 0; mi < 2; mi++) aRowOff[mi] = (uint32_t)(rA + mi * 16) * 128;
#pragma unroll
    for (int g = 0; g < 4; g++) bRowOff[g] = 16384u + (uint32_t)(rB + g * 16) * 128;

    float acc[2][8][4];
#pragma unroll
    for (int mi = 0; mi < 2; mi++)
#pragma unroll
        for (int nt = 0; nt < 8; nt++)
#pragma unroll
            for (int j = 0; j < 4; j++) acc[mi][nt][j] = 0.0f;

    load_chunk(sbase, Arow, Brow, 0, tid);
    cp_commit();
    load_chunk(sbase + STAGE_B, Arow, Brow, 64, tid);
    cp_commit();

    for (int c = 0; c < CH; c++) {
        if (c + 2 < CH) load_chunk(sbase + ((c + 2) % NST) * STAGE_B, Arow, Brow,
                                   (c + 2) * 64, tid);
        cp_commit();
        cp_wait<2>();
        __syncthreads();

        uint32_t stg = sbase + (c % NST) * STAGE_B;
#pragma unroll
        for (int step = 0; step < 4; step++) {
            uint32_t a[2][4];
#pragma unroll
            for (int mi = 0; mi < 2; mi++)
                ldsm4(a[mi], stg + aRowOff[mi] + ((uint32_t)((step * 2 + ksegA) ^ swA) << 4));
            uint32_t b[4][4];
#pragma unroll
            for (int g = 0; g < 4; g++)
                ldsm4(b[g], stg + bRowOff[g] + ((uint32_t)((step * 2 + ksegB) ^ swB) << 4));
#pragma unroll
            for (int mi = 0; mi < 2; mi++)
#pragma unroll
                for (int nt = 0; nt < 8; nt++)
                    mma16816h(acc[mi][nt], a[mi], b[nt >> 1][(nt & 1) * 2],
                              b[nt >> 1][(nt & 1) * 2 + 1]);
        }
        __syncthreads();
    }

    int g = lane >> 2;
    int cl = (lane & 3) * 2;
#pragma unroll
    for (int mi = 0; mi < 2; mi++) {
#pragma unroll
        for (int nt = 0; nt < 8; nt++) {
            int gcol = col0 + n0 + nt * 8 + cl;
            float b0 = bias[gcol], b1 = bias[gcol + 1];
            int r0 = row0 + m0 + mi * 16 + g;
            float2 v0 = make_float2(acc[mi][nt][0] + b0, acc[mi][nt][1] + b1);
            float2 v1 = make_float2(acc[mi][nt][2] + b0, acc[mi][nt][3] + b1);
            *(float2*)(C + (size_t)r0 * CDIM + gcol) = v0;
            *(float2*)(C + (size_t)(r0 + 8) * CDIM + gcol) = v1;
        }
    }
}

// ---------------- mask dtype detection + attend mask -------------------------
__global__ void detect_mask(const unsigned int* __restrict__ m) {
    __shared__ int okf, oki;
    if (threadIdx.x == 0) { okf = 1; oki = 1; }
    __syncthreads();
    for (int i = threadIdx.x; i < 4096; i += blockDim.x) {
        unsigned int w = m[i];
        if (w != 0u && w != 0x3f800000u) okf = 0;
        if (w > 1u) oki = 0;
    }
    __syncthreads();
    if (threadIdx.x == 0) g_maskmode = okf ? 2 : (oki ? 1 : 0);
}

__global__ void build_attend(const void* __restrict__ pm) {
    int w = blockIdx.x;
    int b = w >> 5;
    int wi = w & 31;
    int j = threadIdx.x;
    int p = wi * WINSZ - 128 + j;
    int attend = 1;
    if ((unsigned)p < (unsigned)T_LEN) {
        int mm = g_maskmode;
        size_t im = (size_t)b * T_LEN + p;
        int v;
        if (mm == 0)      v = ((const unsigned char*)pm)[im] != 0;
        else if (mm == 1) v = ((const int*)pm)[im] != 0;
        else              v = ((const float*)pm)[im] != 0.0f;
        attend = !v;
    }
    __shared__ int allb;
    if (j == 0) allb = 1;
    __syncthreads();
    if (!attend) allb = 0;
    __syncthreads();
    if (j == 0 && allb) attend = 0;
    g_attend[w * 512 + j] = (unsigned char)attend;
}

// ---------------- fused rope + split (Q,K) / split (V) ------------------------
__global__ void rope_split(const float* __restrict__ Q, const float* __restrict__ K,
                           const float* __restrict__ V,
                           const float* __restrict__ cosT, const float* __restrict__ sinT,
                           __nv_bfloat16* __restrict__ QHL, __nv_bfloat16* __restrict__ KHL,
                           __nv_bfloat16* __restrict__ VHL) {
    int idx = blockIdx.x * blockDim.x + threadIdx.x;
    int z = blockIdx.y;
    const float* src = (z == 0) ? Q : ((z == 1) ? K : V);
    __nv_bfloat16* dst = (z == 0) ? QHL : ((z == 1) ? KHL : VHL);
    int token = idx >> 9;
    int r = idx & 511;
    int hh = r >> 5;
    int d = r & 31;
    int pos = token & (T_LEN - 1);
    size_t base = (size_t)token * CDIM + hh * HDIM;
    float a = src[base + d];
    float bv = src[base + d + 32];
    float o1, o2;
    if (z < 2) {
        float c1 = cosT[pos * HDIM + d], s1 = sinT[pos * HDIM + d];
        float c2 = cosT[pos * HDIM + d + 32], s2 = sinT[pos * HDIM + d + 32];
        o1 = a * c1 - bv * s1;
        o2 = bv * c2 + a * s2;
    } else { o1 = a; o2 = bv; }
    size_t ob = ((size_t)token * NHEAD + hh) * 128;
    __nv_bfloat16 h1 = __float2bfloat16_rn(o1);
    __nv_bfloat16 h2 = __float2bfloat16_rn(o2);
    dst[ob + d] = h1;
    dst[ob + d + 32] = h2;
    dst[ob + 64 + d] = __float2bfloat16_rn(o1 - __bfloat162float(h1));
    dst[ob + 96 + d] = __float2bfloat16_rn(o2 - __bfloat162float(h2));
}

// ---------------- tensor-core windowed attention ------------------------------
#define ATT_Q_LO 32768
#define ATT_STG 65536
#define ATT_BIAS 131072
#define SMEM_ATTN (1024 + 131072 + 256)

__device__ __forceinline__ void load_kv_chunk(uint32_t stg, const __nv_bfloat16* KHL,
        const __nv_bfloat16* VHL, int b, int h, int p0, int tid) {
#pragma unroll
    for (int i = 0; i < 2; i++) {
        int f = tid + i * 256;
        int r = f >> 3, seg = f & 7;
        int p = p0 + r;
        uint32_t ok = ((unsigned)p < (unsigned)T_LEN) ? 16u : 0u;
        int pc = (p < 0) ? 0 : ((p >= T_LEN) ? (T_LEN - 1) : p);
        const __nv_bfloat16* kk = KHL + (((size_t)(b * T_LEN + pc) * NHEAD + h) << 7) + seg * 8;
        const __nv_bfloat16* vv = VHL + (((size_t)(b * T_LEN + pc) * NHEAD + h) << 7) + seg * 8;
        uint32_t sw = (uint32_t)r * 128 + (uint32_t)(((seg ^ (r & 7)) << 4));
        cp16z(stg + sw, kk, ok);
        cp16z(stg + 8192 + sw, kk + 64, ok);
        cp16z(stg + 16384 + sw, vv, ok);
        cp16z(stg + 24576 + sw, vv + 64, ok);
    }
}

__global__ void __launch_bounds__(256) attn_mma(
        const __nv_bfloat16* __restrict__ QHL, const __nv_bfloat16* __restrict__ KHL,
        const __nv_bfloat16* __restrict__ VHL, __half* __restrict__ AO) {
    extern __shared__ char sm[];
    char* smA = (char*)(((uintptr_t)sm + 1023) & ~(uintptr_t)1023);
    uint32_t sb = smem_u32(smA);
    float* biasP = (float*)(smA + ATT_BIAS);

    int h = blockIdx.x, w = blockIdx.y;
    int b = w >> 5, wi = w & 31;
    int tid = threadIdx.x, wid = tid >> 5, lane = tid & 31;
    int w0 = wid * 32;

    int rA = (lane & 7) + ((lane >> 3) & 1) * 8;
    int ksegA = lane >> 4;
    int rB = (lane & 7) + ((lane >> 4) << 3);
    int ksegB = (lane >> 3) & 1;
    int krV = (lane & 7) + ((lane >> 4) << 3);
    int nsegV = (lane >> 3) & 1;

#pragma unroll
    for (int i = 0; i < 8; i++) {
        int f = tid + i * 256;
        int r = f >> 3, seg = f & 7;
        const __nv_bfloat16* q = QHL + (((size_t)(b * T_LEN + wi * 256 + r) * NHEAD + h) << 7)
                                 + seg * 8;
        uint32_t sw = (uint32_t)r * 128 + (uint32_t)(((seg ^ (r & 7)) << 4));
        cp16(sb + sw, q);
        cp16(sb + ATT_Q_LO + sw, q + 64);
    }
    load_kv_chunk(sb + ATT_STG, KHL, VHL, b, h, wi * 256 - 128, tid);
    cp_commit();
    load_kv_chunk(sb + ATT_STG + 32768, KHL, VHL, b, h, wi * 256 - 64, tid);
    cp_commit();

    float O[2][8][4];
#pragma unroll
    for (int mi = 0; mi < 2; mi++)
#pragma unroll
        for (int nt = 0; nt < 8; nt++)
#pragma unroll
            for (int j = 0; j < 4; j++) O[mi][nt][j] = 0.0f;
    float mrow[4] = {-3e38f, -3e38f, -3e38f, -3e38f};
    float lrow[4] = {0.f, 0.f, 0.f, 0.f};

    for (int c = 0; c < 8; c++) {
        if (c < 6) { cp_wait<1>(); } else { cp_wait<0>(); }
        if (tid < 64)
            biasP[tid] = g_attend[w * 512 + c * 64 + tid] ? 0.0f : -1e30f;
        __syncthreads();

        uint32_t stg = sb + ATT_STG + (uint32_t)(c & 1) * 32768u;

        float S[2][8][4];
#pragma unroll
        for (int mi = 0; mi < 2; mi++)
#pragma unroll
            for (int nt = 0; nt < 8; nt++)
#pragma unroll
                for (int j = 0; j < 4; j++) S[mi][nt][j] = 0.0f;

#pragma unroll
        for (int pass = 0; pass < 3; pass++) {
            uint32_t qoff = (pass == 2) ? (uint32_t)ATT_Q_LO : 0u;
            uint32_t koff = (pass == 1) ? 8192u : 0u;
#pragma unroll
            for (int step = 0; step < 4; step++) {
                uint32_t kb[4][4];
#pragma unroll
                for (int g = 0; g < 4; g++) {
                    int row = g * 16 + rB;
                    ldsm4(kb[g], stg + koff + (uint32_t)row * 128
                          + (uint32_t)(((step * 2 + ksegB) ^ (row & 7)) << 4));
                }
#pragma unroll
                for (int mi = 0; mi < 2; mi++) {
                    int rowQ = w0 + mi * 16 + rA;
                    uint32_t qf[4];
                    ldsm4(qf, sb + qoff + (uint32_t)rowQ * 128
                          + (uint32_t)(((step * 2 + ksegA) ^ (rowQ & 7)) << 4));
#pragma unroll
                    for (int nt = 0; nt < 8; nt++)
                        mma16816(S[mi][nt], qf, kb[nt >> 1][(nt & 1) * 2],
                                 kb[nt >> 1][(nt & 1) * 2 + 1]);
                }
            }
        }

        float2 bias[8];
#pragma unroll
        for (int nt = 0; nt < 8; nt++)
            bias[nt] = *(float2*)&biasP[nt * 8 + 2 * (lane & 3)];
#pragma unroll
        for (int mi = 0; mi < 2; mi++)
#pragma unroll
            for (int nt = 0; nt < 8; nt++) {
                S[mi][nt][0] = fmaf(S[mi][nt][0], 0.125f, bias[nt].x);
                S[mi][nt][1] = fmaf(S[mi][nt][1], 0.125f, bias[nt].y);
                S[mi][nt][2] = fmaf(S[mi][nt][2], 0.125f, bias[nt].x);
                S[mi][nt][3] = fmaf(S[mi][nt][3], 0.125f, bias[nt].y);
            }
#pragma unroll
        for (int mi = 0; mi < 2; mi++)
#pragma unroll
            for (int hh = 0; hh < 2; hh++) {
                int s = mi * 2 + hh;
                float rm = -3e38f;
#pragma unroll
                for (int nt = 0; nt < 8; nt++)
                    rm = fmaxf(rm, fmaxf(S[mi][nt][hh * 2], S[mi][nt][hh * 2 + 1]));
                rm = fmaxf(rm, __shfl_xor_sync(0xffffffffu, rm, 1));
                rm = fmaxf(rm, __shfl_xor_sync(0xffffffffu, rm, 2));
                float mn = fmaxf(mrow[s], rm);
                float sc = __expf(mrow[s] - mn);
                mrow[s] = mn;
                float ls = 0.0f;
#pragma unroll
                for (int nt = 0; nt < 8; nt++) {
                    float p0 = __expf(S[mi][nt][hh * 2] - mn);
                    float p1 = __expf(S[mi][nt][hh * 2 + 1] - mn);
                    S[mi][nt][hh * 2] = p0;
                    S[mi][nt][hh * 2 + 1] = p1;
                    ls += p0 + p1;
                    O[mi][nt][hh * 2] *= sc;
                    O[mi][nt][hh * 2 + 1] *= sc;
                }
                lrow[s] = lrow[s] * sc + ls;
            }

#pragma unroll
        for (int step = 0; step < 4; step++) {
            uint32_t ah[2][4], al[2][4];
#pragma unroll
            for (int mi = 0; mi < 2; mi++)
#pragma unroll
                for (int t2 = 0; t2 < 2; t2++) {
                    float p0 = S[mi][2 * step + t2][0], p1 = S[mi][2 * step + t2][1];
                    float p2 = S[mi][2 * step + t2][2], p3 = S[mi][2 * step + t2][3];
                    uint32_t hA = pack_bf16(p0, p1);
                    uint32_t hB = pack_bf16(p2, p3);
                    ah[mi][t2 * 2] = hA;
                    ah[mi][t2 * 2 + 1] = hB;
                    al[mi][t2 * 2] = pack_bf16(p0 - bf_lo(hA), p1 - bf_hi(hA));
                    al[mi][t2 * 2 + 1] = pack_bf16(p2 - bf_lo(hB), p3 - bf_hi(hB));
                }
            uint32_t vb[4][4];
#pragma unroll
            for (int g = 0; g < 4; g++) {
                int vrow = step * 16 + krV;
                int seg = g * 2 + nsegV;
                ldsm4t(vb[g], stg + 16384u + (uint32_t)vrow * 128
                       + (uint32_t)(((seg ^ (vrow & 7)) << 4)));
            }
#pragma unroll
            for (int mi = 0; mi < 2; mi++)
#pragma unroll
                for (int nt = 0; nt < 8; nt++) {
                    uint32_t b0 = vb[nt >> 1][nt & 1], b1 = vb[nt >> 1][(nt & 1) + 2];
                    mma16816(O[mi][nt], ah[mi], b0, b1);
                    mma16816(O[mi][nt], al[mi], b0, b1);
                }
#pragma unroll
            for (int g = 0; g < 4; g++) {
                int vrow = step * 16 + krV;
                int seg = g * 2 + nsegV;
                ldsm4t(vb[g], stg + 24576u + (uint32_t)vrow * 128
                       + (uint32_t)(((seg ^ (vrow & 7)) << 4)));
            }
#pragma unroll
            for (int mi = 0; mi < 2; mi++)
#pragma unroll
                for (int nt = 0; nt < 8; nt++)
                    mma16816(O[mi][nt], ah[mi], vb[nt >> 1][nt & 1],
                             vb[nt >> 1][(nt & 1) + 2]);
        }

        __syncthreads();
        if (c + 2 < 8) {
            load_kv_chunk(sb + ATT_STG + (uint32_t)(c & 1) * 32768u, KHL, VHL, b, h,
                          wi * 256 - 128 + (c + 2) * 64, tid);
            cp_commit();
        }
    }

#pragma unroll
    for (int s = 0; s < 4; s++) {
        lrow[s] += __shfl_xor_sync(0xffffffffu, lrow[s], 1);
        lrow[s] += __shfl_xor_sync(0xffffffffu, lrow[s], 2);
        lrow[s] = 1.0f / lrow[s];
    }
    int rr = lane >> 2, cc = 2 * (lane & 3);
#pragma unroll
    for (int mi = 0; mi < 2; mi++)
#pragma unroll
        for (int nt = 0; nt < 8; nt++) {
            int tok0 = b * T_LEN + wi * 256 + w0 + mi * 16 + rr;
            int col = h * 64 + nt * 8 + cc;
            float i0 = lrow[mi * 2], i1 = lrow[mi * 2 + 1];
            __half2 v0 = __floats2half2_rn(O[mi][nt][0] * i0, O[mi][nt][1] * i0);
            __half2 v1 = __floats2half2_rn(O[mi][nt][2] * i1, O[mi][nt][3] * i1);
            *(__half2*)(AO + (size_t)tok0 * CDIM + col) = v0;
            *(__half2*)(AO + (size_t)(tok0 + 8) * CDIM + col) = v1;
        }
}

// ---------------- launch --------------------------------------------------------
extern "C" void kernel_launch(void* const* d_in, const int* in_sizes, int n_in,
                              void* d_out, int out_size) {
    const float* x    = (const float*)d_in[0];
    const void*  pm   = d_in[1];
    const float* cosT = (const float*)d_in[2];
    const float* sinT = (const float*)d_in[3];
    const float* Wq   = (const float*)d_in[4];
    const float* bq   = (const float*)d_in[5];
    const float* Wk   = (const float*)d_in[6];
    const float* bk   = (const float*)d_in[7];
    const float* Wv   = (const float*)d_in[8];
    const float* bv   = (const float*)d_in[9];
    const float* Wo   = (const float*)d_in[10];
    const float* bo   = (const float*)d_in[11];
    float* out = (float*)d_out;

    float *Qp, *Kp, *Vp;
    __half *XH, *AOH, *WH;
    __nv_bfloat16 *QHL, *KHL, *VHL;
    cudaGetSymbolAddress((void**)&Qp, g_Q);
    cudaGetSymbolAddress((void**)&Kp, g_K);
    cudaGetSymbolAddress((void**)&Vp, g_V);
    cudaGetSymbolAddress((void**)&XH, g_XH);
    cudaGetSymbolAddress((void**)&AOH, g_AOH);
    cudaGetSymbolAddress((void**)&WH, g_WH);
    cudaGetSymbolAddress((void**)&QHL, g_QHL);
    cudaGetSymbolAddress((void**)&KHL, g_KHL);
    cudaGetSymbolAddress((void**)&VHL, g_VHL);

    cudaFuncSetAttribute(gemm_f16, cudaFuncAttributeMaxDynamicSharedMemorySize, SMEM_GEMM);
    cudaFuncSetAttribute(attn_mma, cudaFuncAttributeMaxDynamicSharedMemorySize, SMEM_ATTN);

    detect_mask<<<1, 256>>>((const unsigned int*)pm);
    build_attend<<<NWIN_TOT, 512>>>(pm);

    // fp32 -> fp16 conversions
    to_half<<<NTOK * CDIM / 1024, 256>>>(x, XH);
    to_half<<<CDIM * CDIM / 1024, 256>>>(Wq, WH + 0 * (size_t)CDIM * CDIM);
    to_half<<<CDIM * CDIM / 1024, 256>>>(Wk, WH + 1 * (size_t)CDIM * CDIM);
    to_half<<<CDIM * CDIM / 1024, 256>>>(Wv, WH + 2 * (size_t)CDIM * CDIM);
    to_half<<<CDIM * CDIM / 1024, 256>>>(Wo, WH + 3 * (size_t)CDIM * CDIM);

    dim3 gg(CDIM / 128, NTOK / 128);
    gemm_f16<<<gg, 256, SMEM_GEMM>>>(XH, WH + 0 * (size_t)CDIM * CDIM, bq, Qp);
    gemm_f16<<<gg, 256, SMEM_GEMM>>>(XH, WH + 1 * (size_t)CDIM * CDIM, bk, Kp);
    gemm_f16<<<gg, 256, SMEM_GEMM>>>(XH, WH + 2 * (size_t)CDIM * CDIM, bv, Vp);

    dim3 rg((NTOK * 512) / 256, 3);
    rope_split<<<rg, 256>>>(Qp, Kp, Vp, cosT, sinT, QHL, KHL, VHL);

    attn_mma<<<dim3(NHEAD, NWIN_TOT), 256, SMEM_ATTN>>>(QHL, KHL, VHL, AOH);

    gemm_f16<<<gg, 256, SMEM_GEMM>>>(AOH, WH + 3 * (size_t)CDIM * CDIM, bo, out);
}

// round 9
// speedup vs baseline: 2.0191x; 1.2422x over previous
#include <cuda_runtime.h>
#include <cuda_bf16.h>
#include <cuda_fp16.h>
#include <cstdint>

#define T_LEN 8192
#define BATCH 2
#define CDIM 1024
#define NHEAD 16
#define HDIM 64
#define WINSZ 256
#define NWIN_TOT 64
#define NTOK (BATCH * T_LEN)     // 16384

// ---------------- scratch ----------------------------------------------------
__device__ float g_Q[(size_t)NTOK * CDIM];
__device__ float g_K[(size_t)NTOK * CDIM];
__device__ float g_V[(size_t)NTOK * CDIM];
__device__ __half g_XH[(size_t)NTOK * CDIM];        // x, fp16
__device__ __half g_AOH[(size_t)NTOK * CDIM];       // attn out, fp16
__device__ __half g_WH[4][(size_t)CDIM * CDIM];     // weights, fp16
__device__ __half g_QH[(size_t)NTOK * NHEAD * 64];  // rope'd Q, fp16 [tok*16+h][64]
__device__ __half g_KH[(size_t)NTOK * NHEAD * 64];
__device__ __half g_VH[(size_t)NTOK * NHEAD * 64];
__device__ unsigned char g_attend[NWIN_TOT * 512];
__device__ int g_maskmode;

// ---------------- helpers ------------------------------------------------------
__device__ __forceinline__ uint32_t smem_u32(const void* p) {
    uint32_t a;
    asm("{ .reg .u64 t; cvta.to.shared.u64 t, %1; cvt.u32.u64 %0, t; }" : "=r"(a) : "l"(p));
    return a;
}
__device__ __forceinline__ void cp16(uint32_t dst, const void* src) {
    asm volatile("cp.async.cg.shared.global [%0], [%1], 16;" :: "r"(dst), "l"(src));
}
__device__ __forceinline__ void cp16z(uint32_t dst, const void* src, uint32_t sz) {
    asm volatile("cp.async.cg.shared.global [%0], [%1], 16, %2;" :: "r"(dst), "l"(src), "r"(sz));
}
__device__ __forceinline__ void cp_commit() { asm volatile("cp.async.commit_group;"); }
template <int N> __device__ __forceinline__ void cp_wait() {
    asm volatile("cp.async.wait_group %0;" :: "n"(N));
}
__device__ __forceinline__ void ldsm4(uint32_t (&r)[4], uint32_t addr) {
    asm volatile("ldmatrix.sync.aligned.m8n8.x4.shared.b16 {%0,%1,%2,%3}, [%4];"
                 : "=r"(r[0]), "=r"(r[1]), "=r"(r[2]), "=r"(r[3]) : "r"(addr));
}
__device__ __forceinline__ void ldsm4t(uint32_t (&r)[4], uint32_t addr) {
    asm volatile("ldmatrix.sync.aligned.m8n8.x4.trans.shared.b16 {%0,%1,%2,%3}, [%4];"
                 : "=r"(r[0]), "=r"(r[1]), "=r"(r[2]), "=r"(r[3]) : "r"(addr));
}
__device__ __forceinline__ void mma16816h(float (&c)[4], const uint32_t (&a)[4],
                                          uint32_t b0, uint32_t b1) {
    asm volatile(
        "mma.sync.aligned.m16n8k16.row.col.f32.f16.f16.f32 "
        "{%0,%1,%2,%3}, {%4,%5,%6,%7}, {%8,%9}, {%0,%1,%2,%3};"
        : "+f"(c[0]), "+f"(c[1]), "+f"(c[2]), "+f"(c[3])
        : "r"(a[0]), "r"(a[1]), "r"(a[2]), "r"(a[3]), "r"(b0), "r"(b1));
}
__device__ __forceinline__ uint32_t pack_f16(float lo, float hi) {
    __half2 h = __floats2half2_rn(lo, hi);
    return *(uint32_t*)&h;
}

// ---------------- fp32 -> fp16 conversion pass ---------------------------------
__global__ void to_half(const float* __restrict__ in, __half* __restrict__ out) {
    int i = blockIdx.x * blockDim.x + threadIdx.x;   // one float4
    float4 v = ((const float4*)in)[i];
    __half2 h01 = __floats2half2_rn(v.x, v.y);
    __half2 h23 = __floats2half2_rn(v.z, v.w);
    ((__half2*)out)[2 * i] = h01;
    ((__half2*)out)[2 * i + 1] = h23;
}

// ---------------- fp16 GEMM (R8-proven) ----------------------------------------
#define GK 1024
#define CH 16
#define NST 3
#define STAGE_B 32768
#define SMEM_GEMM (NST * STAGE_B)

__device__ __forceinline__ void load_chunk(uint32_t stage, const __half* Arow,
                                           const __half* Brow, int kbase, int tid) {
#pragma unroll
    for (int i = 0; i < 4; i++) {
        int f = tid + i * 256;
        int rr = f >> 3, seg = f & 7;
        uint32_t off = rr * 128 + seg * 16;
        uint32_t sw = off ^ ((off >> 3) & 0x70);
        cp16(stage + sw, Arow + (size_t)rr * GK + kbase + seg * 8);
        cp16(stage + 16384 + sw, Brow + (size_t)rr * GK + kbase + seg * 8);
    }
}

__global__ void __launch_bounds__(256) gemm_f16(const __half* __restrict__ A,
        const __half* __restrict__ Bw, const float* __restrict__ bias,
        float* __restrict__ C) {
    extern __shared__ char dsm[];
    uint32_t sbase = smem_u32(dsm);

    int tid = threadIdx.x;
    int wid = tid >> 5, lane = tid & 31;
    int row0 = blockIdx.y * 128;
    int col0 = blockIdx.x * 128;
    int m0 = (wid & 3) * 32;
    int n0 = (wid >> 2) * 64;

    const __half* Arow = A + (size_t)row0 * GK;
    const __half* Brow = Bw + (size_t)col0 * GK;

    int rA = m0 + (lane & 7) + ((lane >> 3) & 1) * 8;
    int ksegA = lane >> 4;
    int swA = rA & 7;
    int rB = n0 + (lane & 7) + ((lane >> 4) << 3);
    int ksegB = (lane >> 3) & 1;
    int swB = rB & 7;

    uint32_t aRowOff[2], bRowOff[4];
#pragma unroll
    for (int mi = 0; mi < 2; mi++) aRowOff[mi] = (uint32_t)(rA + mi * 16) * 128;
#pragma unroll
    for (int g = 0; g < 4; g++) bRowOff[g] = 16384u + (uint32_t)(rB + g * 16) * 128;

    float acc[2][8][4];
#pragma unroll
    for (int mi = 0; mi < 2; mi++)
#pragma unroll
        for (int nt = 0; nt < 8; nt++)
#pragma unroll
            for (int j = 0; j < 4; j++) acc[mi][nt][j] = 0.0f;

    load_chunk(sbase, Arow, Brow, 0, tid);
    cp_commit();
    load_chunk(sbase + STAGE_B, Arow, Brow, 64, tid);
    cp_commit();

    for (int c = 0; c < CH; c++) {
        if (c + 2 < CH) load_chunk(sbase + ((c + 2) % NST) * STAGE_B, Arow, Brow,
                                   (c + 2) * 64, tid);
        cp_commit();
        cp_wait<2>();
        __syncthreads();

        uint32_t stg = sbase + (c % NST) * STAGE_B;
#pragma unroll
        for (int step = 0; step < 4; step++) {
            uint32_t a[2][4];
#pragma unroll
            for (int mi = 0; mi < 2; mi++)
                ldsm4(a[mi], stg + aRowOff[mi] + ((uint32_t)((step * 2 + ksegA) ^ swA) << 4));
            uint32_t b[4][4];
#pragma unroll
            for (int g = 0; g < 4; g++)
                ldsm4(b[g], stg + bRowOff[g] + ((uint32_t)((step * 2 + ksegB) ^ swB) << 4));
#pragma unroll
            for (int mi = 0; mi < 2; mi++)
#pragma unroll
                for (int nt = 0; nt < 8; nt++)
                    mma16816h(acc[mi][nt], a[mi], b[nt >> 1][(nt & 1) * 2],
                              b[nt >> 1][(nt & 1) * 2 + 1]);
        }
        __syncthreads();
    }

    int g = lane >> 2;
    int cl = (lane & 3) * 2;
#pragma unroll
    for (int mi = 0; mi < 2; mi++) {
#pragma unroll
        for (int nt = 0; nt < 8; nt++) {
            int gcol = col0 + n0 + nt * 8 + cl;
            float b0 = bias[gcol], b1 = bias[gcol + 1];
            int r0 = row0 + m0 + mi * 16 + g;
            float2 v0 = make_float2(acc[mi][nt][0] + b0, acc[mi][nt][1] + b1);
            float2 v1 = make_float2(acc[mi][nt][2] + b0, acc[mi][nt][3] + b1);
            *(float2*)(C + (size_t)r0 * CDIM + gcol) = v0;
            *(float2*)(C + (size_t)(r0 + 8) * CDIM + gcol) = v1;
        }
    }
}

// ---------------- mask dtype detection + attend mask -------------------------
__global__ void detect_mask(const unsigned int* __restrict__ m) {
    __shared__ int okf, oki;
    if (threadIdx.x == 0) { okf = 1; oki = 1; }
    __syncthreads();
    for (int i = threadIdx.x; i < 4096; i += blockDim.x) {
        unsigned int w = m[i];
        if (w != 0u && w != 0x3f800000u) okf = 0;
        if (w > 1u) oki = 0;
    }
    __syncthreads();
    if (threadIdx.x == 0) g_maskmode = okf ? 2 : (oki ? 1 : 0);
}

__global__ void build_attend(const void* __restrict__ pm) {
    int w = blockIdx.x;
    int b = w >> 5;
    int wi = w & 31;
    int j = threadIdx.x;
    int p = wi * WINSZ - 128 + j;
    int attend = 1;
    if ((unsigned)p < (unsigned)T_LEN) {
        int mm = g_maskmode;
        size_t im = (size_t)b * T_LEN + p;
        int v;
        if (mm == 0)      v = ((const unsigned char*)pm)[im] != 0;
        else if (mm == 1) v = ((const int*)pm)[im] != 0;
        else              v = ((const float*)pm)[im] != 0.0f;
        attend = !v;
    }
    __shared__ int allb;
    if (j == 0) allb = 1;
    __syncthreads();
    if (!attend) allb = 0;
    __syncthreads();
    if (j == 0 && allb) attend = 0;
    g_attend[w * 512 + j] = (unsigned char)attend;
}

// ---------------- fused rope (Q,K) / passthrough (V) -> fp16 -------------------
__global__ void rope_half(const float* __restrict__ Q, const float* __restrict__ K,
                          const float* __restrict__ V,
                          const float* __restrict__ cosT, const float* __restrict__ sinT,
                          __half* __restrict__ QH, __half* __restrict__ KH,
                          __half* __restrict__ VH) {
    int idx = blockIdx.x * blockDim.x + threadIdx.x;
    int z = blockIdx.y;
    const float* src = (z == 0) ? Q : ((z == 1) ? K : V);
    __half* dst = (z == 0) ? QH : ((z == 1) ? KH : VH);
    int token = idx >> 9;
    int r = idx & 511;
    int hh = r >> 5;
    int d = r & 31;
    int pos = token & (T_LEN - 1);
    size_t base = (size_t)token * CDIM + hh * HDIM;
    float a = src[base + d];
    float bv = src[base + d + 32];
    float o1, o2;
    if (z < 2) {
        float c1 = cosT[pos * HDIM + d], s1 = sinT[pos * HDIM + d];
        float c2 = cosT[pos * HDIM + d + 32], s2 = sinT[pos * HDIM + d + 32];
        o1 = a * c1 - bv * s1;
        o2 = bv * c2 + a * s2;
    } else { o1 = a; o2 = bv; }
    size_t ob = ((size_t)token * NHEAD + hh) * 64;
    dst[ob + d] = __float2half_rn(o1);
    dst[ob + d + 32] = __float2half_rn(o2);
}

// ---------------- tensor-core windowed attention (single-pass fp16) -----------
// smem: Q 32K | stage0 16K (K 8K, V 8K) | stage1 16K | bias
#define ATT_STG 32768
#define ATT_BIAS 65536
#define SMEM_ATTN (1024 + 65536 + 256)

__device__ __forceinline__ void load_kv_chunk(uint32_t stg, const __half* KH,
        const __half* VH, int b, int h, int p0, int tid) {
#pragma unroll
    for (int i = 0; i < 2; i++) {
        int f = tid + i * 256;              // 0..511 = 64 rows x 8 segs
        int r = f >> 3, seg = f & 7;
        int p = p0 + r;
        uint32_t ok = ((unsigned)p < (unsigned)T_LEN) ? 16u : 0u;
        int pc = (p < 0) ? 0 : ((p >= T_LEN) ? (T_LEN - 1) : p);
        const __half* kk = KH + (((size_t)(b * T_LEN + pc) * NHEAD + h) << 6) + seg * 8;
        const __half* vv = VH + (((size_t)(b * T_LEN + pc) * NHEAD + h) << 6) + seg * 8;
        uint32_t sw = (uint32_t)r * 128 + (uint32_t)(((seg ^ (r & 7)) << 4));
        cp16z(stg + sw, kk, ok);
        cp16z(stg + 8192 + sw, vv, ok);
    }
}

__global__ void __launch_bounds__(256) attn_mma(
        const __half* __restrict__ QH, const __half* __restrict__ KH,
        const __half* __restrict__ VH, __half* __restrict__ AO) {
    extern __shared__ char sm[];
    char* smA = (char*)(((uintptr_t)sm + 1023) & ~(uintptr_t)1023);
    uint32_t sb = smem_u32(smA);
    float* biasP = (float*)(smA + ATT_BIAS);

    int h = blockIdx.x, w = blockIdx.y;
    int b = w >> 5, wi = w & 31;
    int tid = threadIdx.x, wid = tid >> 5, lane = tid & 31;
    int w0 = wid * 32;

    int rA = (lane & 7) + ((lane >> 3) & 1) * 8;
    int ksegA = lane >> 4;
    int rB = (lane & 7) + ((lane >> 4) << 3);
    int ksegB = (lane >> 3) & 1;
    int krV = (lane & 7) + ((lane >> 4) << 3);
    int nsegV = (lane >> 3) & 1;

    // Q tile: 256 rows x 128B
#pragma unroll
    for (int i = 0; i < 8; i++) {
        int f = tid + i * 256;
        int r = f >> 3, seg = f & 7;
        const __half* q = QH + (((size_t)(b * T_LEN + wi * 256 + r) * NHEAD + h) << 6)
                          + seg * 8;
        uint32_t sw = (uint32_t)r * 128 + (uint32_t)(((seg ^ (r & 7)) << 4));
        cp16(sb + sw, q);
    }
    load_kv_chunk(sb + ATT_STG, KH, VH, b, h, wi * 256 - 128, tid);
    cp_commit();
    load_kv_chunk(sb + ATT_STG + 16384, KH, VH, b, h, wi * 256 - 64, tid);
    cp_commit();

    float O[2][8][4];
#pragma unroll
    for (int mi = 0; mi < 2; mi++)
#pragma unroll
        for (int nt = 0; nt < 8; nt++)
#pragma unroll
            for (int j = 0; j < 4; j++) O[mi][nt][j] = 0.0f;
    float mrow[4] = {-3e38f, -3e38f, -3e38f, -3e38f};
    float lrow[4] = {0.f, 0.f, 0.f, 0.f};

    for (int c = 0; c < 8; c++) {
        if (c < 6) { cp_wait<1>(); } else { cp_wait<0>(); }
        if (tid < 64)
            biasP[tid] = g_attend[w * 512 + c * 64 + tid] ? 0.0f : -1e30f;
        __syncthreads();

        uint32_t stg = sb + ATT_STG + (uint32_t)(c & 1) * 16384u;

        // ---- S = Q K^T (single fp16 pass)
        float S[2][8][4];
#pragma unroll
        for (int mi = 0; mi < 2; mi++)
#pragma unroll
            for (int nt = 0; nt < 8; nt++)
#pragma unroll
                for (int j = 0; j < 4; j++) S[mi][nt][j] = 0.0f;

#pragma unroll
        for (int step = 0; step < 4; step++) {
            uint32_t kb[4][4];
#pragma unroll
            for (int g = 0; g < 4; g++) {
                int row = g * 16 + rB;
                ldsm4(kb[g], stg + (uint32_t)row * 128
                      + (uint32_t)(((step * 2 + ksegB) ^ (row & 7)) << 4));
            }
#pragma unroll
            for (int mi = 0; mi < 2; mi++) {
                int rowQ = w0 + mi * 16 + rA;
                uint32_t qf[4];
                ldsm4(qf, sb + (uint32_t)rowQ * 128
                      + (uint32_t)(((step * 2 + ksegA) ^ (rowQ & 7)) << 4));
#pragma unroll
                for (int nt = 0; nt < 8; nt++)
                    mma16816h(S[mi][nt], qf, kb[nt >> 1][(nt & 1) * 2],
                              kb[nt >> 1][(nt & 1) * 2 + 1]);
            }
        }

        // ---- scale + bias + online softmax
        float2 bias[8];
#pragma unroll
        for (int nt = 0; nt < 8; nt++)
            bias[nt] = *(float2*)&biasP[nt * 8 + 2 * (lane & 3)];
#pragma unroll
        for (int mi = 0; mi < 2; mi++)
#pragma unroll
            for (int nt = 0; nt < 8; nt++) {
                S[mi][nt][0] = fmaf(S[mi][nt][0], 0.125f, bias[nt].x);
                S[mi][nt][1] = fmaf(S[mi][nt][1], 0.125f, bias[nt].y);
                S[mi][nt][2] = fmaf(S[mi][nt][2], 0.125f, bias[nt].x);
                S[mi][nt][3] = fmaf(S[mi][nt][3], 0.125f, bias[nt].y);
            }
#pragma unroll
        for (int mi = 0; mi < 2; mi++)
#pragma unroll
            for (int hh = 0; hh < 2; hh++) {
                int s = mi * 2 + hh;
                float rm = -3e38f;
#pragma unroll
                for (int nt = 0; nt < 8; nt++)
                    rm = fmaxf(rm, fmaxf(S[mi][nt][hh * 2], S[mi][nt][hh * 2 + 1]));
                rm = fmaxf(rm, __shfl_xor_sync(0xffffffffu, rm, 1));
                rm = fmaxf(rm, __shfl_xor_sync(0xffffffffu, rm, 2));
                float mn = fmaxf(mrow[s], rm);
                float sc = __expf(mrow[s] - mn);
                mrow[s] = mn;
                float ls = 0.0f;
#pragma unroll
                for (int nt = 0; nt < 8; nt++) {
                    float p0 = __expf(S[mi][nt][hh * 2] - mn);
                    float p1 = __expf(S[mi][nt][hh * 2 + 1] - mn);
                    S[mi][nt][hh * 2] = p0;
                    S[mi][nt][hh * 2 + 1] = p1;
                    ls += p0 + p1;
                    O[mi][nt][hh * 2] *= sc;
                    O[mi][nt][hh * 2 + 1] *= sc;
                }
                lrow[s] = lrow[s] * sc + ls;
            }

        // ---- O += P V (single fp16 pass)
#pragma unroll
        for (int step = 0; step < 4; step++) {
            uint32_t ah[2][4];
#pragma unroll
            for (int mi = 0; mi < 2; mi++)
#pragma unroll
                for (int t2 = 0; t2 < 2; t2++) {
                    ah[mi][t2 * 2]     = pack_f16(S[mi][2 * step + t2][0],
                                                  S[mi][2 * step + t2][1]);
                    ah[mi][t2 * 2 + 1] = pack_f16(S[mi][2 * step + t2][2],
                                                  S[mi][2 * step + t2][3]);
                }
            uint32_t vb[4][4];
#pragma unroll
            for (int g = 0; g < 4; g++) {
                int vrow = step * 16 + krV;
                int seg = g * 2 + nsegV;
                ldsm4t(vb[g], stg + 8192u + (uint32_t)vrow * 128
                       + (uint32_t)(((seg ^ (vrow & 7)) << 4)));
            }
#pragma unroll
            for (int mi = 0; mi < 2; mi++)
#pragma unroll
                for (int nt = 0; nt < 8; nt++)
                    mma16816h(O[mi][nt], ah[mi], vb[nt >> 1][nt & 1],
                              vb[nt >> 1][(nt & 1) + 2]);
        }

        __syncthreads();
        if (c + 2 < 8) {
            load_kv_chunk(sb + ATT_STG + (uint32_t)(c & 1) * 16384u, KH, VH, b, h,
                          wi * 256 - 128 + (c + 2) * 64, tid);
            cp_commit();
        }
    }

    // ---- normalize + store fp16
#pragma unroll
    for (int s = 0; s < 4; s++) {
        lrow[s] += __shfl_xor_sync(0xffffffffu, lrow[s], 1);
        lrow[s] += __shfl_xor_sync(0xffffffffu, lrow[s], 2);
        lrow[s] = 1.0f / lrow[s];
    }
    int rr = lane >> 2, cc = 2 * (lane & 3);
#pragma unroll
    for (int mi = 0; mi < 2; mi++)
#pragma unroll
        for (int nt = 0; nt < 8; nt++) {
            int tok0 = b * T_LEN + wi * 256 + w0 + mi * 16 + rr;
            int col = h * 64 + nt * 8 + cc;
            float i0 = lrow[mi * 2], i1 = lrow[mi * 2 + 1];
            __half2 v0 = __floats2half2_rn(O[mi][nt][0] * i0, O[mi][nt][1] * i0);
            __half2 v1 = __floats2half2_rn(O[mi][nt][2] * i1, O[mi][nt][3] * i1);
            *(__half2*)(AO + (size_t)tok0 * CDIM + col) = v0;
            *(__half2*)(AO + (size_t)(tok0 + 8) * CDIM + col) = v1;
        }
}

// ---------------- launch --------------------------------------------------------
extern "C" void kernel_launch(void* const* d_in, const int* in_sizes, int n_in,
                              void* d_out, int out_size) {
    const float* x    = (const float*)d_in[0];
    const void*  pm   = d_in[1];
    const float* cosT = (const float*)d_in[2];
    const float* sinT = (const float*)d_in[3];
    const float* Wq   = (const float*)d_in[4];
    const float* bq   = (const float*)d_in[5];
    const float* Wk   = (const float*)d_in[6];
    const float* bk   = (const float*)d_in[7];
    const float* Wv   = (const float*)d_in[8];
    const float* bv   = (const float*)d_in[9];
    const float* Wo   = (const float*)d_in[10];
    const float* bo   = (const float*)d_in[11];
    float* out = (float*)d_out;

    float *Qp, *Kp, *Vp;
    __half *XH, *AOH, *WH, *QH, *KH, *VH;
    cudaGetSymbolAddress((void**)&Qp, g_Q);
    cudaGetSymbolAddress((void**)&Kp, g_K);
    cudaGetSymbolAddress((void**)&Vp, g_V);
    cudaGetSymbolAddress((void**)&XH, g_XH);
    cudaGetSymbolAddress((void**)&AOH, g_AOH);
    cudaGetSymbolAddress((void**)&WH, g_WH);
    cudaGetSymbolAddress((void**)&QH, g_QH);
    cudaGetSymbolAddress((void**)&KH, g_KH);
    cudaGetSymbolAddress((void**)&VH, g_VH);

    cudaFuncSetAttribute(gemm_f16, cudaFuncAttributeMaxDynamicSharedMemorySize, SMEM_GEMM);
    cudaFuncSetAttribute(attn_mma, cudaFuncAttributeMaxDynamicSharedMemorySize, SMEM_ATTN);

    detect_mask<<<1, 256>>>((const unsigned int*)pm);
    build_attend<<<NWIN_TOT, 512>>>(pm);

    to_half<<<NTOK * CDIM / 1024, 256>>>(x, XH);
    to_half<<<CDIM * CDIM / 1024, 256>>>(Wq, WH + 0 * (size_t)CDIM * CDIM);
    to_half<<<CDIM * CDIM / 1024, 256>>>(Wk, WH + 1 * (size_t)CDIM * CDIM);
    to_half<<<CDIM * CDIM / 1024, 256>>>(Wv, WH + 2 * (size_t)CDIM * CDIM);
    to_half<<<CDIM * CDIM / 1024, 256>>>(Wo, WH + 3 * (size_t)CDIM * CDIM);

    dim3 gg(CDIM / 128, NTOK / 128);
    gemm_f16<<<gg, 256, SMEM_GEMM>>>(XH, WH + 0 * (size_t)CDIM * CDIM, bq, Qp);
    gemm_f16<<<gg, 256, SMEM_GEMM>>>(XH, WH + 1 * (size_t)CDIM * CDIM, bk, Kp);
    gemm_f16<<<gg, 256, SMEM_GEMM>>>(XH, WH + 2 * (size_t)CDIM * CDIM, bv, Vp);

    dim3 rg((NTOK * 512) / 256, 3);
    rope_half<<<rg, 256>>>(Qp, Kp, Vp, cosT, sinT, QH, KH, VH);

    attn_mma<<<dim3(NHEAD, NWIN_TOT), 256, SMEM_ATTN>>>(QH, KH, VH, AOH);

    gemm_f16<<<gg, 256, SMEM_GEMM>>>(AOH, WH + 3 * (size_t)CDIM * CDIM, bo, out);
}

// round 10
// speedup vs baseline: 2.2783x; 1.1284x over previous
#include <cuda_runtime.h>
#include <cuda_bf16.h>
#include <cuda_fp16.h>
#include <cstdint>

#define T_LEN 8192
#define BATCH 2
#define CDIM 1024
#define NHEAD 16
#define HDIM 64
#define WINSZ 256
#define NWIN_TOT 64
#define NTOK (BATCH * T_LEN)     // 16384

// ---------------- scratch ----------------------------------------------------
__device__ __half g_XH[(size_t)NTOK * CDIM];        // x, fp16
__device__ __half g_AOH[(size_t)NTOK * CDIM];       // attn out, fp16
__device__ __half g_WH[4][(size_t)CDIM * CDIM];     // weights, fp16
__device__ __half g_QH[(size_t)NTOK * NHEAD * 64];  // rope'd Q fp16 [tok*16+h][64]
__device__ __half g_KH[(size_t)NTOK * NHEAD * 64];
__device__ __half g_VH[(size_t)NTOK * NHEAD * 64];
__device__ unsigned char g_attend[NWIN_TOT * 512];
__device__ int g_maskmode;

// ---------------- helpers ------------------------------------------------------
__device__ __forceinline__ uint32_t smem_u32(const void* p) {
    uint32_t a;
    asm("{ .reg .u64 t; cvta.to.shared.u64 t, %1; cvt.u32.u64 %0, t; }" : "=r"(a) : "l"(p));
    return a;
}
__device__ __forceinline__ void cp16(uint32_t dst, const void* src) {
    asm volatile("cp.async.cg.shared.global [%0], [%1], 16;" :: "r"(dst), "l"(src));
}
__device__ __forceinline__ void cp16z(uint32_t dst, const void* src, uint32_t sz) {
    asm volatile("cp.async.cg.shared.global [%0], [%1], 16, %2;" :: "r"(dst), "l"(src), "r"(sz));
}
__device__ __forceinline__ void cp_commit() { asm volatile("cp.async.commit_group;"); }
template <int N> __device__ __forceinline__ void cp_wait() {
    asm volatile("cp.async.wait_group %0;" :: "n"(N));
}
__device__ __forceinline__ void ldsm4(uint32_t (&r)[4], uint32_t addr) {
    asm volatile("ldmatrix.sync.aligned.m8n8.x4.shared.b16 {%0,%1,%2,%3}, [%4];"
                 : "=r"(r[0]), "=r"(r[1]), "=r"(r[2]), "=r"(r[3]) : "r"(addr));
}
__device__ __forceinline__ void ldsm4t(uint32_t (&r)[4], uint32_t addr) {
    asm volatile("ldmatrix.sync.aligned.m8n8.x4.trans.shared.b16 {%0,%1,%2,%3}, [%4];"
                 : "=r"(r[0]), "=r"(r[1]), "=r"(r[2]), "=r"(r[3]) : "r"(addr));
}
__device__ __forceinline__ void mma16816h(float (&c)[4], const uint32_t (&a)[4],
                                          uint32_t b0, uint32_t b1) {
    asm volatile(
        "mma.sync.aligned.m16n8k16.row.col.f32.f16.f16.f32 "
        "{%0,%1,%2,%3}, {%4,%5,%6,%7}, {%8,%9}, {%0,%1,%2,%3};"
        : "+f"(c[0]), "+f"(c[1]), "+f"(c[2]), "+f"(c[3])
        : "r"(a[0]), "r"(a[1]), "r"(a[2]), "r"(a[3]), "r"(b0), "r"(b1));
}
__device__ __forceinline__ uint32_t pack_f16(float lo, float hi) {
    __half2 h = __floats2half2_rn(lo, hi);
    return *(uint32_t*)&h;
}

// ---------------- fp32 -> fp16 conversion pass ---------------------------------
__global__ void to_half(const float* __restrict__ in, __half* __restrict__ out) {
    int i = blockIdx.x * blockDim.x + threadIdx.x;
    float4 v = ((const float4*)in)[i];
    __half2 h01 = __floats2half2_rn(v.x, v.y);
    __half2 h23 = __floats2half2_rn(v.z, v.w);
    ((__half2*)out)[2 * i] = h01;
    ((__half2*)out)[2 * i + 1] = h23;
}

// ---------------- fp16 GEMM common pieces --------------------------------------
#define GK 1024
#define CH 16
#define NST 3
#define STAGE_B 32768
#define SMEM_GEMM (NST * STAGE_B)

__device__ __forceinline__ void load_chunk(uint32_t stage, const __half* Arow,
                                           const __half* Brow, int kbase, int tid) {
#pragma unroll
    for (int i = 0; i < 4; i++) {
        int f = tid + i * 256;
        int rr = f >> 3, seg = f & 7;
        uint32_t off = rr * 128 + seg * 16;
        uint32_t sw = off ^ ((off >> 3) & 0x70);
        cp16(stage + sw, Arow + (size_t)rr * GK + kbase + seg * 8);
        cp16(stage + 16384 + sw, Brow + (size_t)rr * GK + kbase + seg * 8);
    }
}

// mainloop shared by both GEMM kernels; leaves results in acc
__device__ __forceinline__ void gemm_mainloop(char* dsm, const __half* Arow,
        const __half* Brow, int tid, int wid, int lane, int m0, int n0,
        float (&acc)[2][8][4]) {
    uint32_t sbase = smem_u32(dsm);

    int rA = m0 + (lane & 7) + ((lane >> 3) & 1) * 8;
    int ksegA = lane >> 4;
    int swA = rA & 7;
    int rB = n0 + (lane & 7) + ((lane >> 4) << 3);
    int ksegB = (lane >> 3) & 1;
    int swB = rB & 7;

    uint32_t aRowOff[2], bRowOff[4];
#pragma unroll
    for (int mi = 0; mi < 2; mi++) aRowOff[mi] = (uint32_t)(rA + mi * 16) * 128;
#pragma unroll
    for (int g = 0; g < 4; g++) bRowOff[g] = 16384u + (uint32_t)(rB + g * 16) * 128;

#pragma unroll
    for (int mi = 0; mi < 2; mi++)
#pragma unroll
        for (int nt = 0; nt < 8; nt++)
#pragma unroll
            for (int j = 0; j < 4; j++) acc[mi][nt][j] = 0.0f;

    load_chunk(sbase, Arow, Brow, 0, tid);
    cp_commit();
    load_chunk(sbase + STAGE_B, Arow, Brow, 64, tid);
    cp_commit();

    for (int c = 0; c < CH; c++) {
        if (c + 2 < CH) load_chunk(sbase + ((c + 2) % NST) * STAGE_B, Arow, Brow,
                                   (c + 2) * 64, tid);
        cp_commit();
        cp_wait<2>();
        __syncthreads();

        uint32_t stg = sbase + (c % NST) * STAGE_B;
#pragma unroll
        for (int step = 0; step < 4; step++) {
            uint32_t a[2][4];
#pragma unroll
            for (int mi = 0; mi < 2; mi++)
                ldsm4(a[mi], stg + aRowOff[mi] + ((uint32_t)((step * 2 + ksegA) ^ swA) << 4));
            uint32_t b[4][4];
#pragma unroll
            for (int g = 0; g < 4; g++)
                ldsm4(b[g], stg + bRowOff[g] + ((uint32_t)((step * 2 + ksegB) ^ swB) << 4));
#pragma unroll
            for (int mi = 0; mi < 2; mi++)
#pragma unroll
                for (int nt = 0; nt < 8; nt++)
                    mma16816h(acc[mi][nt], a[mi], b[nt >> 1][(nt & 1) * 2],
                              b[nt >> 1][(nt & 1) * 2 + 1]);
        }
        __syncthreads();
    }
}

// ---------------- fused QKV GEMM: bias + (rope) + fp16 store in attn layout ----
// grid (8, 128, 3): z selects Q/K/V.
__global__ void __launch_bounds__(256) gemm_qkv(const __half* __restrict__ A,
        const __half* __restrict__ WHbase,
        const float* __restrict__ bq, const float* __restrict__ bk,
        const float* __restrict__ bv,
        const float* __restrict__ cosT, const float* __restrict__ sinT,
        __half* __restrict__ QH, __half* __restrict__ KH, __half* __restrict__ VH) {
    extern __shared__ char dsm[];
    int which = blockIdx.z;
    const __half* W = WHbase + (size_t)which * CDIM * CDIM;
    const float* bias = (which == 0) ? bq : ((which == 1) ? bk : bv);
    __half* outH = (which == 0) ? QH : ((which == 1) ? KH : VH);

    int tid = threadIdx.x;
    int wid = tid >> 5, lane = tid & 31;
    int row0 = blockIdx.y * 128;
    int col0 = blockIdx.x * 128;
    int m0 = (wid & 3) * 32;
    int n0 = (wid >> 2) * 64;

    float acc[2][8][4];
    gemm_mainloop(dsm, A + (size_t)row0 * GK, W + (size_t)col0 * GK,
                  tid, wid, lane, m0, n0, acc);

    int g = lane >> 2;
    int cl = (lane & 3) * 2;
    int hh = (col0 + n0) >> 6;              // warp spans exactly one head

    // bias add (reference adds bias before rope)
#pragma unroll
    for (int mi = 0; mi < 2; mi++)
#pragma unroll
        for (int nt = 0; nt < 8; nt++) {
            int gcol = col0 + n0 + nt * 8 + cl;
            float b0 = bias[gcol], b1 = bias[gcol + 1];
            acc[mi][nt][0] += b0; acc[mi][nt][1] += b1;
            acc[mi][nt][2] += b0; acc[mi][nt][3] += b1;
        }

    if (which < 2) {   // rope on Q, K
#pragma unroll
        for (int mi = 0; mi < 2; mi++) {
            int r0 = row0 + m0 + mi * 16 + g;
            int pos0 = r0 & (T_LEN - 1);      // r0+8 never crosses the 8192 boundary
            const float* c0 = cosT + (size_t)pos0 * HDIM;
            const float* s0 = sinT + (size_t)pos0 * HDIM;
            const float* c1 = c0 + 8 * HDIM;
            const float* s1 = s0 + 8 * HDIM;
#pragma unroll
            for (int nt = 0; nt < 4; nt++) {
                int d = nt * 8 + cl;
                float2 cA0 = *(const float2*)(c0 + d), sA0 = *(const float2*)(s0 + d);
                float2 cB0 = *(const float2*)(c0 + d + 32), sB0 = *(const float2*)(s0 + d + 32);
                float2 cA1 = *(const float2*)(c1 + d), sA1 = *(const float2*)(s1 + d);
                float2 cB1 = *(const float2*)(c1 + d + 32), sB1 = *(const float2*)(s1 + d + 32);
                float a, b;
                a = acc[mi][nt][0]; b = acc[mi][nt + 4][0];
                acc[mi][nt][0]     = a * cA0.x - b * sA0.x;
                acc[mi][nt + 4][0] = b * cB0.x + a * sB0.x;
                a = acc[mi][nt][1]; b = acc[mi][nt + 4][1];
                acc[mi][nt][1]     = a * cA0.y - b * sA0.y;
                acc[mi][nt + 4][1] = b * cB0.y + a * sB0.y;
                a = acc[mi][nt][2]; b = acc[mi][nt + 4][2];
                acc[mi][nt][2]     = a * cA1.x - b * sA1.x;
                acc[mi][nt + 4][2] = b * cB1.x + a * sB1.x;
                a = acc[mi][nt][3]; b = acc[mi][nt + 4][3];
                acc[mi][nt][3]     = a * cA1.y - b * sA1.y;
                acc[mi][nt + 4][3] = b * cB1.y + a * sB1.y;
            }
        }
    }

    // store fp16 in [tok*16 + h][64] layout
#pragma unroll
    for (int mi = 0; mi < 2; mi++) {
        int r0 = row0 + m0 + mi * 16 + g;
        __half* o0 = outH + ((size_t)r0 * NHEAD + hh) * 64;
        __half* o1 = outH + ((size_t)(r0 + 8) * NHEAD + hh) * 64;
#pragma unroll
        for (int nt = 0; nt < 8; nt++) {
            int d = nt * 8 + cl;
            __half2 v0 = __floats2half2_rn(acc[mi][nt][0], acc[mi][nt][1]);
            __half2 v1 = __floats2half2_rn(acc[mi][nt][2], acc[mi][nt][3]);
            *(__half2*)(o0 + d) = v0;
            *(__half2*)(o1 + d) = v1;
        }
    }
}

// ---------------- O-projection GEMM: fp32 out + bias ---------------------------
__global__ void __launch_bounds__(256) gemm_f16(const __half* __restrict__ A,
        const __half* __restrict__ Bw, const float* __restrict__ bias,
        float* __restrict__ C) {
    extern __shared__ char dsm[];
    int tid = threadIdx.x;
    int wid = tid >> 5, lane = tid & 31;
    int row0 = blockIdx.y * 128;
    int col0 = blockIdx.x * 128;
    int m0 = (wid & 3) * 32;
    int n0 = (wid >> 2) * 64;

    float acc[2][8][4];
    gemm_mainloop(dsm, A + (size_t)row0 * GK, Bw + (size_t)col0 * GK,
                  tid, wid, lane, m0, n0, acc);

    int g = lane >> 2;
    int cl = (lane & 3) * 2;
#pragma unroll
    for (int mi = 0; mi < 2; mi++) {
#pragma unroll
        for (int nt = 0; nt < 8; nt++) {
            int gcol = col0 + n0 + nt * 8 + cl;
            float b0 = bias[gcol], b1 = bias[gcol + 1];
            int r0 = row0 + m0 + mi * 16 + g;
            float2 v0 = make_float2(acc[mi][nt][0] + b0, acc[mi][nt][1] + b1);
            float2 v1 = make_float2(acc[mi][nt][2] + b0, acc[mi][nt][3] + b1);
            *(float2*)(C + (size_t)r0 * CDIM + gcol) = v0;
            *(float2*)(C + (size_t)(r0 + 8) * CDIM + gcol) = v1;
        }
    }
}

// ---------------- mask dtype detection + attend mask -------------------------
__global__ void detect_mask(const unsigned int* __restrict__ m) {
    __shared__ int okf, oki;
    if (threadIdx.x == 0) { okf = 1; oki = 1; }
    __syncthreads();
    for (int i = threadIdx.x; i < 4096; i += blockDim.x) {
        unsigned int w = m[i];
        if (w != 0u && w != 0x3f800000u) okf = 0;
        if (w > 1u) oki = 0;
    }
    __syncthreads();
    if (threadIdx.x == 0) g_maskmode = okf ? 2 : (oki ? 1 : 0);
}

__global__ void build_attend(const void* __restrict__ pm) {
    int w = blockIdx.x;
    int b = w >> 5;
    int wi = w & 31;
    int j = threadIdx.x;
    int p = wi * WINSZ - 128 + j;
    int attend = 1;
    if ((unsigned)p < (unsigned)T_LEN) {
        int mm = g_maskmode;
        size_t im = (size_t)b * T_LEN + p;
        int v;
        if (mm == 0)      v = ((const unsigned char*)pm)[im] != 0;
        else if (mm == 1) v = ((const int*)pm)[im] != 0;
        else              v = ((const float*)pm)[im] != 0.0f;
        attend = !v;
    }
    __shared__ int allb;
    if (j == 0) allb = 1;
    __syncthreads();
    if (!attend) allb = 0;
    __syncthreads();
    if (j == 0 && allb) attend = 0;
    g_attend[w * 512 + j] = (unsigned char)attend;
}

// ---------------- tensor-core windowed attention (single-pass fp16) -----------
#define ATT_STG 32768
#define ATT_BIAS 65536
#define SMEM_ATTN (1024 + 65536 + 256)

__device__ __forceinline__ void load_kv_chunk(uint32_t stg, const __half* KH,
        const __half* VH, int b, int h, int p0, int tid) {
#pragma unroll
    for (int i = 0; i < 2; i++) {
        int f = tid + i * 256;
        int r = f >> 3, seg = f & 7;
        int p = p0 + r;
        uint32_t ok = ((unsigned)p < (unsigned)T_LEN) ? 16u : 0u;
        int pc = (p < 0) ? 0 : ((p >= T_LEN) ? (T_LEN - 1) : p);
        const __half* kk = KH + (((size_t)(b * T_LEN + pc) * NHEAD + h) << 6) + seg * 8;
        const __half* vv = VH + (((size_t)(b * T_LEN + pc) * NHEAD + h) << 6) + seg * 8;
        uint32_t sw = (uint32_t)r * 128 + (uint32_t)(((seg ^ (r & 7)) << 4));
        cp16z(stg + sw, kk, ok);
        cp16z(stg + 8192 + sw, vv, ok);
    }
}

__global__ void __launch_bounds__(256) attn_mma(
        const __half* __restrict__ QH, const __half* __restrict__ KH,
        const __half* __restrict__ VH, __half* __restrict__ AO) {
    extern __shared__ char sm[];
    char* smA = (char*)(((uintptr_t)sm + 1023) & ~(uintptr_t)1023);
    uint32_t sb = smem_u32(smA);
    float* biasP = (float*)(smA + ATT_BIAS);

    int h = blockIdx.x, w = blockIdx.y;
    int b = w >> 5, wi = w & 31;
    int tid = threadIdx.x, wid = tid >> 5, lane = tid & 31;
    int w0 = wid * 32;

    int rA = (lane & 7) + ((lane >> 3) & 1) * 8;
    int ksegA = lane >> 4;
    int rB = (lane & 7) + ((lane >> 4) << 3);
    int ksegB = (lane >> 3) & 1;
    int krV = (lane & 7) + ((lane >> 4) << 3);
    int nsegV = (lane >> 3) & 1;

#pragma unroll
    for (int i = 0; i < 8; i++) {
        int f = tid + i * 256;
        int r = f >> 3, seg = f & 7;
        const __half* q = QH + (((size_t)(b * T_LEN + wi * 256 + r) * NHEAD + h) << 6)
                          + seg * 8;
        uint32_t sw = (uint32_t)r * 128 + (uint32_t)(((seg ^ (r & 7)) << 4));
        cp16(sb + sw, q);
    }
    load_kv_chunk(sb + ATT_STG, KH, VH, b, h, wi * 256 - 128, tid);
    cp_commit();
    load_kv_chunk(sb + ATT_STG + 16384, KH, VH, b, h, wi * 256 - 64, tid);
    cp_commit();

    float O[2][8][4];
#pragma unroll
    for (int mi = 0; mi < 2; mi++)
#pragma unroll
        for (int nt = 0; nt < 8; nt++)
#pragma unroll
            for (int j = 0; j < 4; j++) O[mi][nt][j] = 0.0f;
    float mrow[4] = {-3e38f, -3e38f, -3e38f, -3e38f};
    float lrow[4] = {0.f, 0.f, 0.f, 0.f};

    for (int c = 0; c < 8; c++) {
        if (c < 6) { cp_wait<1>(); } else { cp_wait<0>(); }
        if (tid < 64)
            biasP[tid] = g_attend[w * 512 + c * 64 + tid] ? 0.0f : -1e30f;
        __syncthreads();

        uint32_t stg = sb + ATT_STG + (uint32_t)(c & 1) * 16384u;

        float S[2][8][4];
#pragma unroll
        for (int mi = 0; mi < 2; mi++)
#pragma unroll
            for (int nt = 0; nt < 8; nt++)
#pragma unroll
                for (int j = 0; j < 4; j++) S[mi][nt][j] = 0.0f;

#pragma unroll
        for (int step = 0; step < 4; step++) {
            uint32_t kb[4][4];
#pragma unroll
            for (int g = 0; g < 4; g++) {
                int row = g * 16 + rB;
                ldsm4(kb[g], stg + (uint32_t)row * 128
                      + (uint32_t)(((step * 2 + ksegB) ^ (row & 7)) << 4));
            }
#pragma unroll
            for (int mi = 0; mi < 2; mi++) {
                int rowQ = w0 + mi * 16 + rA;
                uint32_t qf[4];
                ldsm4(qf, sb + (uint32_t)rowQ * 128
                      + (uint32_t)(((step * 2 + ksegA) ^ (rowQ & 7)) << 4));
#pragma unroll
                for (int nt = 0; nt < 8; nt++)
                    mma16816h(S[mi][nt], qf, kb[nt >> 1][(nt & 1) * 2],
                              kb[nt >> 1][(nt & 1) * 2 + 1]);
            }
        }

        float2 bias[8];
#pragma unroll
        for (int nt = 0; nt < 8; nt++)
            bias[nt] = *(float2*)&biasP[nt * 8 + 2 * (lane & 3)];
#pragma unroll
        for (int mi = 0; mi < 2; mi++)
#pragma unroll
            for (int nt = 0; nt < 8; nt++) {
                S[mi][nt][0] = fmaf(S[mi][nt][0], 0.125f, bias[nt].x);
                S[mi][nt][1] = fmaf(S[mi][nt][1], 0.125f, bias[nt].y);
                S[mi][nt][2] = fmaf(S[mi][nt][2], 0.125f, bias[nt].x);
                S[mi][nt][3] = fmaf(S[mi][nt][3], 0.125f, bias[nt].y);
            }
#pragma unroll
        for (int mi = 0; mi < 2; mi++)
#pragma unroll
            for (int hh = 0; hh < 2; hh++) {
                int s = mi * 2 + hh;
                float rm = -3e38f;
#pragma unroll
                for (int nt = 0; nt < 8; nt++)
                    rm = fmaxf(rm, fmaxf(S[mi][nt][hh * 2], S[mi][nt][hh * 2 + 1]));
                rm = fmaxf(rm, __shfl_xor_sync(0xffffffffu, rm, 1));
                rm = fmaxf(rm, __shfl_xor_sync(0xffffffffu, rm, 2));
                float mn = fmaxf(mrow[s], rm);
                float sc = __expf(mrow[s] - mn);
                mrow[s] = mn;
                float ls = 0.0f;
#pragma unroll
                for (int nt = 0; nt < 8; nt++) {
                    float p0 = __expf(S[mi][nt][hh * 2] - mn);
                    float p1 = __expf(S[mi][nt][hh * 2 + 1] - mn);
                    S[mi][nt][hh * 2] = p0;
                    S[mi][nt][hh * 2 + 1] = p1;
                    ls += p0 + p1;
                    O[mi][nt][hh * 2] *= sc;
                    O[mi][nt][hh * 2 + 1] *= sc;
                }
                lrow[s] = lrow[s] * sc + ls;
            }

#pragma unroll
        for (int step = 0; step < 4; step++) {
            uint32_t ah[2][4];
#pragma unroll
            for (int mi = 0; mi < 2; mi++)
#pragma unroll
                for (int t2 = 0; t2 < 2; t2++) {
                    ah[mi][t2 * 2]     = pack_f16(S[mi][2 * step + t2][0],
                                                  S[mi][2 * step + t2][1]);
                    ah[mi][t2 * 2 + 1] = pack_f16(S[mi][2 * step + t2][2],
                                                  S[mi][2 * step + t2][3]);
                }
            uint32_t vb[4][4];
#pragma unroll
            for (int g = 0; g < 4; g++) {
                int vrow = step * 16 + krV;
                int seg = g * 2 + nsegV;
                ldsm4t(vb[g], stg + 8192u + (uint32_t)vrow * 128
                       + (uint32_t)(((seg ^ (vrow & 7)) << 4)));
            }
#pragma unroll
            for (int mi = 0; mi < 2; mi++)
#pragma unroll
                for (int nt = 0; nt < 8; nt++)
                    mma16816h(O[mi][nt], ah[mi], vb[nt >> 1][nt & 1],
                              vb[nt >> 1][(nt & 1) + 2]);
        }

        __syncthreads();
        if (c + 2 < 8) {
            load_kv_chunk(sb + ATT_STG + (uint32_t)(c & 1) * 16384u, KH, VH, b, h,
                          wi * 256 - 128 + (c + 2) * 64, tid);
            cp_commit();
        }
    }

#pragma unroll
    for (int s = 0; s < 4; s++) {
        lrow[s] += __shfl_xor_sync(0xffffffffu, lrow[s], 1);
        lrow[s] += __shfl_xor_sync(0xffffffffu, lrow[s], 2);
        lrow[s] = 1.0f / lrow[s];
    }
    int rr = lane >> 2, cc = 2 * (lane & 3);
#pragma unroll
    for (int mi = 0; mi < 2; mi++)
#pragma unroll
        for (int nt = 0; nt < 8; nt++) {
            int tok0 = b * T_LEN + wi * 256 + w0 + mi * 16 + rr;
            int col = h * 64 + nt * 8 + cc;
            float i0 = lrow[mi * 2], i1 = lrow[mi * 2 + 1];
            __half2 v0 = __floats2half2_rn(O[mi][nt][0] * i0, O[mi][nt][1] * i0);
            __half2 v1 = __floats2half2_rn(O[mi][nt][2] * i1, O[mi][nt][3] * i1);
            *(__half2*)(AO + (size_t)tok0 * CDIM + col) = v0;
            *(__half2*)(AO + (size_t)(tok0 + 8) * CDIM + col) = v1;
        }
}

// ---------------- launch --------------------------------------------------------
extern "C" void kernel_launch(void* const* d_in, const int* in_sizes, int n_in,
                              void* d_out, int out_size) {
    const float* x    = (const float*)d_in[0];
    const void*  pm   = d_in[1];
    const float* cosT = (const float*)d_in[2];
    const float* sinT = (const float*)d_in[3];
    const float* Wq   = (const float*)d_in[4];
    const float* bq   = (const float*)d_in[5];
    const float* Wk   = (const float*)d_in[6];
    const float* bk   = (const float*)d_in[7];
    const float* Wv   = (const float*)d_in[8];
    const float* bv   = (const float*)d_in[9];
    const float* Wo   = (const float*)d_in[10];
    const float* bo   = (const float*)d_in[11];
    float* out = (float*)d_out;

    __half *XH, *AOH, *WH, *QH, *KH, *VH;
    cudaGetSymbolAddress((void**)&XH, g_XH);
    cudaGetSymbolAddress((void**)&AOH, g_AOH);
    cudaGetSymbolAddress((void**)&WH, g_WH);
    cudaGetSymbolAddress((void**)&QH, g_QH);
    cudaGetSymbolAddress((void**)&KH, g_KH);
    cudaGetSymbolAddress((void**)&VH, g_VH);

    cudaFuncSetAttribute(gemm_qkv, cudaFuncAttributeMaxDynamicSharedMemorySize, SMEM_GEMM);
    cudaFuncSetAttribute(gemm_f16, cudaFuncAttributeMaxDynamicSharedMemorySize, SMEM_GEMM);
    cudaFuncSetAttribute(attn_mma, cudaFuncAttributeMaxDynamicSharedMemorySize, SMEM_ATTN);

    detect_mask<<<1, 256>>>((const unsigned int*)pm);
    build_attend<<<NWIN_TOT, 512>>>(pm);

    to_half<<<NTOK * CDIM / 1024, 256>>>(x, XH);
    to_half<<<CDIM * CDIM / 1024, 256>>>(Wq, WH + 0 * (size_t)CDIM * CDIM);
    to_half<<<CDIM * CDIM / 1024, 256>>>(Wk, WH + 1 * (size_t)CDIM * CDIM);
    to_half<<<CDIM * CDIM / 1024, 256>>>(Wv, WH + 2 * (size_t)CDIM * CDIM);
    to_half<<<CDIM * CDIM / 1024, 256>>>(Wo, WH + 3 * (size_t)CDIM * CDIM);

    dim3 gq(CDIM / 128, NTOK / 128, 3);
    gemm_qkv<<<gq, 256, SMEM_GEMM>>>(XH, WH, bq, bk, bv, cosT, sinT, QH, KH, VH);

    attn_mma<<<dim3(NHEAD, NWIN_TOT), 256, SMEM_ATTN>>>(QH, KH, VH, AOH);

    dim3 gg(CDIM / 128, NTOK / 128);
    gemm_f16<<<gg, 256, SMEM_GEMM>>>(AOH, WH + 3 * (size_t)CDIM * CDIM, bo, out);
}